// round 6
// baseline (speedup 1.0000x reference)
#include <cuda_runtime.h>
#include <math.h>

// ---------------- problem constants ----------------
#define BB   16
#define NN   512
#define HH   12
#define DKK  64
#define DD   768           // HH*DKK
#define BH   (BB*HH)       // 192
#define MROWS (BB*NN)      // 8192
#define KNN  153           // max(1, int(0.3*512))

// ---------------- scratch (device globals, no allocation) ----------------
__device__ float g_qkv[3 * BH * NN * DKK];     // [3][B][H][N][DK]  75.5 MB
__device__ float g_msg[MROWS * DD];            // [B*N, 768]
__device__ float g_y1 [MROWS * DD];
__device__ float g_preln[MROWS * DD];
__device__ unsigned char g_mask[BB * NN * NN]; // [B,N,N]

// =====================================================================
// kNN mask: per (b, n) row, bitonic-sort 512 keys ((f32bits<<32)|idx),
// take 153 smallest (ties broken by lower index — matches jax top_k).
// =====================================================================
__global__ void __launch_bounds__(256)
build_mask(const float* __restrict__ dist)
{
    int bid = blockIdx.x;
    int b = bid >> 9, n = bid & 511;
    unsigned char* mrow = g_mask + ((b << 9) + n) * NN;
    int tid = threadIdx.x;

    if (n == 0) {                       // super node row: all true
        for (int m = tid; m < NN; m += 256) mrow[m] = 1;
        return;
    }

    __shared__ unsigned long long key[512];
    for (int m = tid; m < NN; m += 256) {
        float v = (m == 0) ? 0.0f : dist[(b * 511 + (n - 1)) * 511 + (m - 1)];
        key[m] = ((unsigned long long)__float_as_uint(v) << 32) | (unsigned)m;
    }
    __syncthreads();

    // bitonic sort ascending
    for (int k = 2; k <= 512; k <<= 1) {
        for (int j = k >> 1; j > 0; j >>= 1) {
            for (int i = tid; i < 512; i += 256) {
                int ixj = i ^ j;
                if (ixj > i) {
                    bool up = ((i & k) == 0);
                    unsigned long long a = key[i], c = key[ixj];
                    if ((a > c) == up) { key[i] = c; key[ixj] = a; }
                }
            }
            __syncthreads();
        }
    }

    for (int m = tid; m < NN; m += 256) mrow[m] = 0;
    __syncthreads();
    for (int s = tid; s < KNN; s += 256)
        mrow[(int)(key[s] & 511u)] = 1;
    if (tid == 0) mrow[0] = 1;          // super node column always true
}

// =====================================================================
// Generic 64x64x16 fp32 GEMM  C = A @ W^T + bias, with mode epilogues.
//   mode 0: A = x,    z selects Q/K/V weights; store remapped to [3,B,H,N,DK]
//   mode 1: A = g_msg, silu epilogue -> g_y1
//   mode 2: A = g_y1,  + bias + residual(x) -> g_preln
// =====================================================================
__global__ void __launch_bounds__(256)
gemm_proj(const float* __restrict__ xin,
          const float* __restrict__ W0, const float* __restrict__ W1, const float* __restrict__ W2,
          const float* __restrict__ B0, const float* __restrict__ B1, const float* __restrict__ B2,
          int mode)
{
    const int K = DD;
    int bn = blockIdx.x, bm = blockIdx.y, z = blockIdx.z;
    const float* A  = (mode == 0) ? xin : (mode == 1) ? g_msg : g_y1;
    const float* W  = (z == 0) ? W0 : (z == 1) ? W1 : W2;
    const float* Bb = (z == 0) ? B0 : (z == 1) ? B1 : B2;

    __shared__ float As[16][64];
    __shared__ float Bs[16][64];

    int tid  = threadIdx.x;
    int lrow = tid >> 2;
    int lc4  = (tid & 3) << 2;
    const float* Ald = A + (bm * 64 + lrow) * K + lc4;
    const float* Wld = W + (bn * 64 + lrow) * K + lc4;

    int tx = tid & 15, ty = tid >> 4;
    float acc[4][4];
    #pragma unroll
    for (int i = 0; i < 4; i++)
        #pragma unroll
        for (int j = 0; j < 4; j++) acc[i][j] = 0.0f;

    for (int k0 = 0; k0 < K; k0 += 16) {
        float4 a4 = *(const float4*)(Ald + k0);
        float4 w4 = *(const float4*)(Wld + k0);
        As[lc4+0][lrow] = a4.x; As[lc4+1][lrow] = a4.y;
        As[lc4+2][lrow] = a4.z; As[lc4+3][lrow] = a4.w;
        Bs[lc4+0][lrow] = w4.x; Bs[lc4+1][lrow] = w4.y;
        Bs[lc4+2][lrow] = w4.z; Bs[lc4+3][lrow] = w4.w;
        __syncthreads();
        #pragma unroll
        for (int kk = 0; kk < 16; kk++) {
            float4 av = *(const float4*)&As[kk][ty << 2];
            float4 bv = *(const float4*)&Bs[kk][tx << 2];
            float a[4] = {av.x, av.y, av.z, av.w};
            float b[4] = {bv.x, bv.y, bv.z, bv.w};
            #pragma unroll
            for (int i = 0; i < 4; i++)
                #pragma unroll
                for (int j = 0; j < 4; j++)
                    acc[i][j] += a[i] * b[j];
        }
        __syncthreads();
    }

    int row0 = bm * 64 + (ty << 2);
    int col0 = bn * 64 + (tx << 2);
    #pragma unroll
    for (int i = 0; i < 4; i++) {
        int m = row0 + i;
        #pragma unroll
        for (int j = 0; j < 4; j++) {
            int n = col0 + j;
            float v = acc[i][j] + Bb[n];
            if (mode == 0) {
                int b = m >> 9, nn = m & 511, h = n >> 6, dk = n & 63;
                g_qkv[((((z * BB + b) * HH + h) * NN + nn) << 6) + dk] = v;
            } else if (mode == 1) {
                g_y1[m * DD + n] = v / (1.0f + expf(-v));
            } else {
                g_preln[m * DD + n] = v + xin[m * DD + n];
            }
        }
    }
}

// =====================================================================
// scores: per (b,h) S = Q K^T * 0.125, masked -> attn slice of d_out
// =====================================================================
__global__ void __launch_bounds__(256)
gemm_scores(float* __restrict__ attn)
{
    int bn = blockIdx.x, bm = blockIdx.y, z = blockIdx.z;   // z = b*12+h
    const float* Q  = g_qkv + z * (NN * DKK);
    const float* Km = g_qkv + BH * NN * DKK + z * (NN * DKK);

    __shared__ float As[16][64];
    __shared__ float Bs[16][64];

    int tid  = threadIdx.x;
    int lrow = tid >> 2;
    int lc4  = (tid & 3) << 2;
    const float* Ald = Q  + (bm * 64 + lrow) * DKK + lc4;
    const float* Bld = Km + (bn * 64 + lrow) * DKK + lc4;

    int tx = tid & 15, ty = tid >> 4;
    float acc[4][4];
    #pragma unroll
    for (int i = 0; i < 4; i++)
        #pragma unroll
        for (int j = 0; j < 4; j++) acc[i][j] = 0.0f;

    for (int k0 = 0; k0 < DKK; k0 += 16) {
        float4 a4 = *(const float4*)(Ald + k0);
        float4 b4 = *(const float4*)(Bld + k0);
        As[lc4+0][lrow] = a4.x; As[lc4+1][lrow] = a4.y;
        As[lc4+2][lrow] = a4.z; As[lc4+3][lrow] = a4.w;
        Bs[lc4+0][lrow] = b4.x; Bs[lc4+1][lrow] = b4.y;
        Bs[lc4+2][lrow] = b4.z; Bs[lc4+3][lrow] = b4.w;
        __syncthreads();
        #pragma unroll
        for (int kk = 0; kk < 16; kk++) {
            float4 av = *(const float4*)&As[kk][ty << 2];
            float4 bv = *(const float4*)&Bs[kk][tx << 2];
            float a[4] = {av.x, av.y, av.z, av.w};
            float b[4] = {bv.x, bv.y, bv.z, bv.w};
            #pragma unroll
            for (int i = 0; i < 4; i++)
                #pragma unroll
                for (int j = 0; j < 4; j++)
                    acc[i][j] += a[i] * b[j];
        }
        __syncthreads();
    }

    int b = z / HH;
    int row0 = bm * 64 + (ty << 2);
    int col0 = bn * 64 + (tx << 2);
    #pragma unroll
    for (int i = 0; i < 4; i++) {
        int n = row0 + i;
        const unsigned char* mr = g_mask + ((b << 9) + n) * NN;
        #pragma unroll
        for (int j = 0; j < 4; j++) {
            int mcol = col0 + j;
            float v = acc[i][j] * 0.125f;
            attn[(size_t)(z * NN + n) * NN + mcol] = mr[mcol] ? v : -1e12f;
        }
    }
}

// =====================================================================
// softmax over last dim (512) of attn, in place
// =====================================================================
__global__ void __launch_bounds__(128)
softmax512(float* __restrict__ attn)
{
    float* p = attn + (size_t)blockIdx.x * NN;
    int tid = threadIdx.x;
    float v[4];
    #pragma unroll
    for (int i = 0; i < 4; i++) v[i] = p[tid + (i << 7)];

    float mx = fmaxf(fmaxf(v[0], v[1]), fmaxf(v[2], v[3]));
    #pragma unroll
    for (int o = 16; o > 0; o >>= 1)
        mx = fmaxf(mx, __shfl_xor_sync(0xffffffffu, mx, o));
    __shared__ float sm[4], ss[4];
    int wp = tid >> 5, ln = tid & 31;
    if (ln == 0) sm[wp] = mx;
    __syncthreads();
    mx = fmaxf(fmaxf(sm[0], sm[1]), fmaxf(sm[2], sm[3]));

    float s = 0.0f;
    #pragma unroll
    for (int i = 0; i < 4; i++) { v[i] = expf(v[i] - mx); s += v[i]; }
    #pragma unroll
    for (int o = 16; o > 0; o >>= 1)
        s += __shfl_xor_sync(0xffffffffu, s, o);
    if (ln == 0) ss[wp] = s;
    __syncthreads();
    s = ss[0] + ss[1] + ss[2] + ss[3];
    float inv = 1.0f / s;
    #pragma unroll
    for (int i = 0; i < 4; i++) p[tid + (i << 7)] = v[i] * inv;
}

// =====================================================================
// msg = attn @ V  per (b,h): M=512, N=64, K=512; store [B,N,H*DK]
// =====================================================================
__global__ void __launch_bounds__(256)
gemm_msg(const float* __restrict__ attn)
{
    int bm = blockIdx.y, z = blockIdx.z;
    const float* A = attn + (size_t)z * (NN * NN);
    const float* V = g_qkv + 2 * BH * NN * DKK + z * (NN * DKK);

    __shared__ float As[16][64];
    __shared__ float Bs[16][64];

    int tid  = threadIdx.x;
    int lrow = tid >> 2;
    int lc4  = (tid & 3) << 2;
    const float* Ald = A + (bm * 64 + lrow) * NN + lc4;
    int brow = tid >> 4;
    int bc4  = (tid & 15) << 2;

    int tx = tid & 15, ty = tid >> 4;
    float acc[4][4];
    #pragma unroll
    for (int i = 0; i < 4; i++)
        #pragma unroll
        for (int j = 0; j < 4; j++) acc[i][j] = 0.0f;

    for (int k0 = 0; k0 < NN; k0 += 16) {
        float4 a4 = *(const float4*)(Ald + k0);
        float4 b4 = *(const float4*)(V + (k0 + brow) * DKK + bc4);
        As[lc4+0][lrow] = a4.x; As[lc4+1][lrow] = a4.y;
        As[lc4+2][lrow] = a4.z; As[lc4+3][lrow] = a4.w;
        *(float4*)&Bs[brow][bc4] = b4;
        __syncthreads();
        #pragma unroll
        for (int kk = 0; kk < 16; kk++) {
            float4 av = *(const float4*)&As[kk][ty << 2];
            float4 bv = *(const float4*)&Bs[kk][tx << 2];
            float a[4] = {av.x, av.y, av.z, av.w};
            float b[4] = {bv.x, bv.y, bv.z, bv.w};
            #pragma unroll
            for (int i = 0; i < 4; i++)
                #pragma unroll
                for (int j = 0; j < 4; j++)
                    acc[i][j] += a[i] * b[j];
        }
        __syncthreads();
    }

    int b = z / HH, h = z % HH;
    int row0 = bm * 64 + (ty << 2);
    int col0 = (tx << 2);
    #pragma unroll
    for (int i = 0; i < 4; i++) {
        int n = row0 + i;
        #pragma unroll
        for (int j = 0; j < 4; j++) {
            int dk = col0 + j;
            g_msg[(b * NN + n) * DD + h * DKK + dk] = acc[i][j];
        }
    }
}

// =====================================================================
// layernorm over 768, rows = B*N
// =====================================================================
__global__ void __launch_bounds__(256)
layernorm(const float* __restrict__ gam, const float* __restrict__ bet,
          float* __restrict__ out)
{
    int row = blockIdx.x;
    const float* p = g_preln + row * DD;
    int tid = threadIdx.x;
    float x0 = p[tid], x1 = p[tid + 256], x2 = p[tid + 512];

    __shared__ float red[256];
    red[tid] = x0 + x1 + x2;
    __syncthreads();
    for (int o = 128; o > 0; o >>= 1) {
        if (tid < o) red[tid] += red[tid + o];
        __syncthreads();
    }
    float mu = red[0] * (1.0f / 768.0f);
    __syncthreads();

    float d0 = x0 - mu, d1 = x1 - mu, d2 = x2 - mu;
    red[tid] = d0 * d0 + d1 * d1 + d2 * d2;
    __syncthreads();
    for (int o = 128; o > 0; o >>= 1) {
        if (tid < o) red[tid] += red[tid + o];
        __syncthreads();
    }
    float var = red[0] * (1.0f / 768.0f);
    float inv = 1.0f / sqrtf(var + 1e-6f);

    float* o = out + row * DD;
    o[tid]       = d0 * inv * gam[tid]       + bet[tid];
    o[tid + 256] = d1 * inv * gam[tid + 256] + bet[tid + 256];
    o[tid + 512] = d2 * inv * gam[tid + 512] + bet[tid + 512];
}

// =====================================================================
// launch
// =====================================================================
extern "C" void kernel_launch(void* const* d_in, const int* in_sizes, int n_in,
                              void* d_out, int out_size)
{
    const float* x    = (const float*)d_in[0];
    const float* dist = (const float*)d_in[1];
    const float* q_w  = (const float*)d_in[2];
    const float* q_b  = (const float*)d_in[3];
    const float* k_w  = (const float*)d_in[4];
    const float* k_b  = (const float*)d_in[5];
    const float* v_w  = (const float*)d_in[6];
    const float* v_b  = (const float*)d_in[7];
    const float* s1_w = (const float*)d_in[8];
    const float* s1_b = (const float*)d_in[9];
    const float* s2_w = (const float*)d_in[10];
    const float* s2_b = (const float*)d_in[11];
    const float* ln_g = (const float*)d_in[12];
    const float* ln_b = (const float*)d_in[13];

    float* out  = (float*)d_out;                    // [B,N,768]
    float* attn = out + (size_t)MROWS * DD;         // [B,H,1,N,N]

    // kNN mask
    build_mask<<<BB * NN, 256>>>(dist);

    // Q,K,V projections (z = 0/1/2)
    gemm_proj<<<dim3(DD / 64, MROWS / 64, 3), 256>>>(
        x, q_w, k_w, v_w, q_b, k_b, v_b, 0);

    // masked scores -> attn slice of d_out
    gemm_scores<<<dim3(NN / 64, NN / 64, BH), 256>>>(attn);

    // softmax in place
    softmax512<<<BH * NN, 128>>>(attn);

    // msg = attn @ V -> g_msg [B,N,768]
    gemm_msg<<<dim3(1, NN / 64, BH), 256>>>(attn);

    // s1 (silu) -> g_y1
    gemm_proj<<<dim3(DD / 64, MROWS / 64, 1), 256>>>(
        x, s1_w, s1_w, s1_w, s1_b, s1_b, s1_b, 1);

    // s2 + residual -> g_preln
    gemm_proj<<<dim3(DD / 64, MROWS / 64, 1), 256>>>(
        x, s2_w, s2_w, s2_w, s2_b, s2_b, s2_b, 2);

    // layernorm -> out
    layernorm<<<MROWS, 256>>>(ln_g, ln_b, out);
}

// round 8
// speedup vs baseline: 1.5930x; 1.5930x over previous
#include <cuda_runtime.h>
#include <cuda_bf16.h>
#include <math.h>
#include <stdint.h>

#define BB 16
#define NN 512
#define HH 12
#define DKK 64
#define DD 768
#define BHZ 192
#define MROWS 8192
#define KNN 153

typedef __nv_bfloat16 bf16;

__device__ bf16 g_xh[(size_t)MROWS*DD], g_xl[(size_t)MROWS*DD];
__device__ bf16 g_wh[(size_t)5*DD*DD],  g_wl[(size_t)5*DD*DD];
__device__ bf16 g_qh[(size_t)BHZ*NN*DKK], g_ql[(size_t)BHZ*NN*DKK];
__device__ bf16 g_kh[(size_t)BHZ*NN*DKK], g_kl[(size_t)BHZ*NN*DKK];
__device__ bf16 g_vh[(size_t)BHZ*NN*DKK], g_vl[(size_t)BHZ*NN*DKK];
__device__ bf16 g_mh[(size_t)MROWS*DD],  g_ml[(size_t)MROWS*DD];
__device__ bf16 g_y1h[(size_t)MROWS*DD], g_y1l[(size_t)MROWS*DD];
__device__ float g_preln[(size_t)MROWS*DD];
__device__ unsigned char g_mask[(size_t)BB*NN*NN];

__device__ __forceinline__ void split2(float v, bf16& h, bf16& l){
    h = __float2bfloat16(v); l = __float2bfloat16(v - __bfloat162float(h));
}
__device__ __forceinline__ uint32_t pk(bf16 a, bf16 b){
    uint16_t x = *(uint16_t*)&a, y = *(uint16_t*)&b;
    return (uint32_t)x | ((uint32_t)y << 16);
}
__device__ __forceinline__ void mma16816(float* c, const uint32_t* a, const uint32_t* b){
    asm volatile("mma.sync.aligned.m16n8k16.row.col.f32.bf16.bf16.f32 "
        "{%0,%1,%2,%3}, {%4,%5,%6,%7}, {%8,%9}, {%0,%1,%2,%3};"
        : "+f"(c[0]),"+f"(c[1]),"+f"(c[2]),"+f"(c[3])
        : "r"(a[0]),"r"(a[1]),"r"(a[2]),"r"(a[3]),"r"(b[0]),"r"(b[1]));
}

// ---- fp32 -> bf16 hi/lo ----
__global__ void __launch_bounds__(256)
conv_split(const float* __restrict__ src, int sel, size_t off, int n4)
{
    int i = blockIdx.x*256 + threadIdx.x;
    if (i >= n4) return;
    bf16 *hi = sel ? g_wh+off : g_xh, *lo = sel ? g_wl+off : g_xl;
    float4 v = ((const float4*)src)[i];
    bf16 h[4], l[4];
    split2(v.x,h[0],l[0]); split2(v.y,h[1],l[1]); split2(v.z,h[2],l[2]); split2(v.w,h[3],l[3]);
    ((uint2*)hi)[i] = *(uint2*)h; ((uint2*)lo)[i] = *(uint2*)l;
}

// ---- kNN mask (proven) ----
__global__ void __launch_bounds__(256)
build_mask(const float* __restrict__ dist)
{
    int b = blockIdx.x>>9, n = blockIdx.x&511, tid = threadIdx.x;
    unsigned char* mrow = g_mask + ((size_t)(b<<9)+n)*NN;
    if (n == 0){ for (int m=tid;m<NN;m+=256) mrow[m]=1; return; }
    __shared__ unsigned long long key[512];
    for (int m=tid;m<NN;m+=256){
        float v = (m==0)?0.0f:dist[(size_t)(b*511+(n-1))*511+(m-1)];
        key[m] = ((unsigned long long)__float_as_uint(v)<<32) | (unsigned)m;
    }
    __syncthreads();
    for (int k=2;k<=512;k<<=1) for (int j=k>>1;j>0;j>>=1){
        for (int i=tid;i<512;i+=256){
            int x = i^j;
            if (x>i){ bool up=((i&k)==0); unsigned long long a=key[i],c=key[x];
                if ((a>c)==up){ key[i]=c; key[x]=a; } }
        }
        __syncthreads();
    }
    for (int m=tid;m<NN;m+=256) mrow[m]=0;
    __syncthreads();
    for (int s=tid;s<KNN;s+=256) mrow[(int)(key[s]&511u)]=1;
    if (tid==0) mrow[0]=1;
}

// stage 128 rows x 64 bf16 (row-major, ld stride) into pair layout [k2][row], stride 132
__device__ __forceinline__ void stage128(uint32_t* dst, const bf16* src, int row0, int k0, int ld){
    for (int i = threadIdx.x; i < 1024; i += 256){
        int r = i>>3, s = i&7;
        uint4 v = *(const uint4*)(src + (size_t)(row0+r)*ld + k0 + s*8);
        uint32_t* p = (uint32_t*)&v;
        dst[(s*4+0)*132+r]=p[0]; dst[(s*4+1)*132+r]=p[1];
        dst[(s*4+2)*132+r]=p[2]; dst[(s*4+3)*132+r]=p[3];
    }
}

// ---- big GEMM: C[128x128] = A[.x768] @ W^T + bias (mma.sync bf16x3) ----
#define SMEM_BIG (16896*4)
__global__ void __launch_bounds__(256)
gemm_big(int asel, int widx0, const float* __restrict__ Bb0, const float* __restrict__ Bb1,
         const float* __restrict__ Bb2, const float* __restrict__ xres, int mode)
{
    extern __shared__ uint32_t sm[];
    uint32_t *sAh=sm, *sAl=sm+4224, *sBh=sm+8448, *sBl=sm+12672;
    const int bn=blockIdx.x, bm=blockIdx.y, z=blockIdx.z;
    const bf16 *Ah = asel==0?g_xh: asel==1?g_mh:g_y1h;
    const bf16 *Al = asel==0?g_xl: asel==1?g_ml:g_y1l;
    const bf16 *Wh = g_wh + (size_t)(widx0+z)*DD*DD;
    const bf16 *Wl = g_wl + (size_t)(widx0+z)*DD*DD;
    const float* Bb = z==0?Bb0 : z==1?Bb1 : Bb2;
    int tid=threadIdx.x, wid=tid>>5, lane=tid&31;
    int wm=wid&3, wn=wid>>2, tq=lane>>2, tr=lane&3;

    float acc[2][8][4];
    #pragma unroll
    for (int a=0;a<2;a++)
        #pragma unroll
        for (int b=0;b<8;b++)
            #pragma unroll
            for (int d=0;d<4;d++) acc[a][b][d]=0.0f;

    for (int c = 0; c < 12; c++){
        stage128(sAh, Ah, bm*128, c*64, DD);
        stage128(sAl, Al, bm*128, c*64, DD);
        stage128(sBh, Wh, bn*128, c*64, DD);
        stage128(sBl, Wl, bn*128, c*64, DD);
        __syncthreads();
        #pragma unroll
        for (int kk = 0; kk < 4; kk++){
            int kb = kk*8;
            uint32_t a_h[2][4], a_l[2][4], b_h[8][2], b_l[8][2];
            #pragma unroll
            for (int am=0;am<2;am++){
                int cm = wm*32 + am*16 + tq;
                a_h[am][0]=sAh[(kb+tr)*132+cm];   a_h[am][1]=sAh[(kb+tr)*132+cm+8];
                a_h[am][2]=sAh[(kb+tr+4)*132+cm]; a_h[am][3]=sAh[(kb+tr+4)*132+cm+8];
                a_l[am][0]=sAl[(kb+tr)*132+cm];   a_l[am][1]=sAl[(kb+tr)*132+cm+8];
                a_l[am][2]=sAl[(kb+tr+4)*132+cm]; a_l[am][3]=sAl[(kb+tr+4)*132+cm+8];
            }
            #pragma unroll
            for (int an=0;an<8;an++){
                int cn = wn*64 + an*8 + tq;
                b_h[an][0]=sBh[(kb+tr)*132+cn]; b_h[an][1]=sBh[(kb+tr+4)*132+cn];
                b_l[an][0]=sBl[(kb+tr)*132+cn]; b_l[an][1]=sBl[(kb+tr+4)*132+cn];
            }
            #pragma unroll
            for (int am=0;am<2;am++)
                #pragma unroll
                for (int an=0;an<8;an++){
                    mma16816(acc[am][an], a_h[am], b_h[an]);
                    mma16816(acc[am][an], a_h[am], b_l[an]);
                    mma16816(acc[am][an], a_l[am], b_h[an]);
                }
        }
        __syncthreads();
    }

    #pragma unroll
    for (int am=0;am<2;am++)
    #pragma unroll
    for (int rr=0;rr<2;rr++){
        int row = bm*128 + wm*32 + am*16 + tq + rr*8;
        #pragma unroll
        for (int an=0;an<8;an++){
            int col = bn*128 + wn*64 + an*8 + tr*2;
            float v0 = acc[am][an][rr*2]   + Bb[col];
            float v1 = acc[am][an][rr*2+1] + Bb[col+1];
            if (mode == 0){
                int b=row>>9, tok=row&511, h=col>>6, dk=col&63;
                size_t off = ((size_t)(b*HH+h)*NN+tok)*DKK + dk;
                bf16 h0,l0,h1,l1; split2(v0,h0,l0); split2(v1,h1,l1);
                bf16 *dh, *dl;
                if (z==0){ dh=g_qh; dl=g_ql; } else if (z==1){ dh=g_kh; dl=g_kl; }
                else { dh=g_vh; dl=g_vl; }
                *(uint32_t*)(dh+off) = pk(h0,h1);
                *(uint32_t*)(dl+off) = pk(l0,l1);
            } else if (mode == 1){
                v0 = v0/(1.0f+expf(-v0)); v1 = v1/(1.0f+expf(-v1));
                bf16 h0,l0,h1,l1; split2(v0,h0,l0); split2(v1,h1,l1);
                size_t off = (size_t)row*DD + col;
                *(uint32_t*)(g_y1h+off) = pk(h0,h1);
                *(uint32_t*)(g_y1l+off) = pk(l0,l1);
            } else {
                size_t off = (size_t)row*DD + col;
                float2 xr = *(const float2*)(xres+off);
                float2 o; o.x = v0+xr.x; o.y = v1+xr.y;
                *(float2*)(g_preln+off) = o;
            }
        }
    }
}

// ---- scores: S[128x128] = Q @ K^T (K=64), mask*0.125 -> attn ----
#define SMEM_SC (16896*4)
__global__ void __launch_bounds__(256)
gemm_scores_tc(float* __restrict__ attn)
{
    extern __shared__ uint32_t sm[];
    uint32_t *sAh=sm, *sAl=sm+4224, *sBh=sm+8448, *sBl=sm+12672;
    const int bn=blockIdx.x, bm=blockIdx.y, z=blockIdx.z;
    const bf16 *Qh=g_qh+(size_t)z*NN*DKK, *Ql=g_ql+(size_t)z*NN*DKK;
    const bf16 *Kh=g_kh+(size_t)z*NN*DKK, *Kl=g_kl+(size_t)z*NN*DKK;
    int tid=threadIdx.x, wid=tid>>5, lane=tid&31;
    int wm=wid&3, wn=wid>>2, tq=lane>>2, tr=lane&3;

    float acc[2][8][4];
    #pragma unroll
    for (int a=0;a<2;a++)
        #pragma unroll
        for (int b=0;b<8;b++)
            #pragma unroll
            for (int d=0;d<4;d++) acc[a][b][d]=0.0f;

    stage128(sAh, Qh, bm*128, 0, DKK);
    stage128(sAl, Ql, bm*128, 0, DKK);
    stage128(sBh, Kh, bn*128, 0, DKK);
    stage128(sBl, Kl, bn*128, 0, DKK);
    __syncthreads();
    #pragma unroll
    for (int kk = 0; kk < 4; kk++){
        int kb = kk*8;
        uint32_t a_h[2][4], a_l[2][4], b_h[8][2], b_l[8][2];
        #pragma unroll
        for (int am=0;am<2;am++){
            int cm = wm*32 + am*16 + tq;
            a_h[am][0]=sAh[(kb+tr)*132+cm];   a_h[am][1]=sAh[(kb+tr)*132+cm+8];
            a_h[am][2]=sAh[(kb+tr+4)*132+cm]; a_h[am][3]=sAh[(kb+tr+4)*132+cm+8];
            a_l[am][0]=sAl[(kb+tr)*132+cm];   a_l[am][1]=sAl[(kb+tr)*132+cm+8];
            a_l[am][2]=sAl[(kb+tr+4)*132+cm]; a_l[am][3]=sAl[(kb+tr+4)*132+cm+8];
        }
        #pragma unroll
        for (int an=0;an<8;an++){
            int cn = wn*64 + an*8 + tq;
            b_h[an][0]=sBh[(kb+tr)*132+cn]; b_h[an][1]=sBh[(kb+tr+4)*132+cn];
            b_l[an][0]=sBl[(kb+tr)*132+cn]; b_l[an][1]=sBl[(kb+tr+4)*132+cn];
        }
        #pragma unroll
        for (int am=0;am<2;am++)
            #pragma unroll
            for (int an=0;an<8;an++){
                mma16816(acc[am][an], a_h[am], b_h[an]);
                mma16816(acc[am][an], a_h[am], b_l[an]);
                mma16816(acc[am][an], a_l[am], b_h[an]);
            }
    }

    int b = z/HH;
    #pragma unroll
    for (int am=0;am<2;am++)
    #pragma unroll
    for (int rr=0;rr<2;rr++){
        int row = bm*128 + wm*32 + am*16 + tq + rr*8;
        const unsigned char* mr = g_mask + ((size_t)(b<<9)+row)*NN;
        #pragma unroll
        for (int an=0;an<8;an++){
            int col = bn*128 + wn*64 + an*8 + tr*2;
            float2 o;
            o.x = mr[col]   ? acc[am][an][rr*2]*0.125f   : -1e12f;
            o.y = mr[col+1] ? acc[am][an][rr*2+1]*0.125f : -1e12f;
            *(float2*)(attn + ((size_t)z*NN+row)*NN + col) = o;
        }
    }
}

// ---- softmax 512 (proven) ----
__global__ void __launch_bounds__(128)
softmax512(float* __restrict__ attn)
{
    float* p = attn + (size_t)blockIdx.x*NN;
    int tid = threadIdx.x;
    float v[4];
    #pragma unroll
    for (int i=0;i<4;i++) v[i]=p[tid+(i<<7)];
    float mx = fmaxf(fmaxf(v[0],v[1]),fmaxf(v[2],v[3]));
    #pragma unroll
    for (int o=16;o>0;o>>=1) mx=fmaxf(mx,__shfl_xor_sync(0xffffffffu,mx,o));
    __shared__ float smx[4], ssm[4];
    int wp=tid>>5, ln=tid&31;
    if (ln==0) smx[wp]=mx;
    __syncthreads();
    mx = fmaxf(fmaxf(smx[0],smx[1]),fmaxf(smx[2],smx[3]));
    float s=0.0f;
    #pragma unroll
    for (int i=0;i<4;i++){ v[i]=expf(v[i]-mx); s+=v[i]; }
    #pragma unroll
    for (int o=16;o>0;o>>=1) s+=__shfl_xor_sync(0xffffffffu,s,o);
    if (ln==0) ssm[wp]=s;
    __syncthreads();
    s = ssm[0]+ssm[1]+ssm[2]+ssm[3];
    float inv = 1.0f/s;
    #pragma unroll
    for (int i=0;i<4;i++) p[tid+(i<<7)]=v[i]*inv;
}

// ---- msg = attn @ V : block 128x64, K=512 (8 chunks) ----
#define SMEM_MSG ((4224*2 + 2176*2)*4)
__global__ void __launch_bounds__(256)
gemm_msg_tc(const float* __restrict__ attn)
{
    extern __shared__ uint32_t sm[];
    uint32_t *sAh=sm, *sAl=sm+4224, *sBh=sm+8448, *sBl=sm+8448+2176;
    const int bm=blockIdx.x, z=blockIdx.y;
    const float* A = attn + (size_t)z*NN*NN;
    const bf16 *Vh=g_vh+(size_t)z*NN*DKK, *Vl=g_vl+(size_t)z*NN*DKK;
    int tid=threadIdx.x, wid=tid>>5, lane=tid&31;
    int wm=wid&3, wn=wid>>2, tq=lane>>2, tr=lane&3;

    float acc[2][4][4];
    #pragma unroll
    for (int a=0;a<2;a++)
        #pragma unroll
        for (int b=0;b<4;b++)
            #pragma unroll
            for (int d=0;d<4;d++) acc[a][b][d]=0.0f;

    for (int c = 0; c < 8; c++){
        // A: fp32 attn -> hi/lo pairs [k2][row], stride 132
        for (int i = tid; i < 1024; i += 256){
            int r = i>>3, s = i&7;
            const float* p = A + (size_t)(bm*128+r)*NN + c*64 + s*8;
            float4 f0 = ((const float4*)p)[0], f1 = ((const float4*)p)[1];
            float f[8] = {f0.x,f0.y,f0.z,f0.w,f1.x,f1.y,f1.z,f1.w};
            #pragma unroll
            for (int j=0;j<4;j++){
                bf16 h0,l0,h1,l1;
                split2(f[2*j],h0,l0); split2(f[2*j+1],h1,l1);
                sAh[(s*4+j)*132+r]=pk(h0,h1);
                sAl[(s*4+j)*132+r]=pk(l0,l1);
            }
        }
        // B: V pairs along tok -> [k2][dk], stride 68
        {
            int k2 = tid>>3, s = tid&7;
            uint4 e = *(const uint4*)(Vh + (size_t)(c*64+2*k2)*DKK + s*8);
            uint4 o = *(const uint4*)(Vh + (size_t)(c*64+2*k2+1)*DKK + s*8);
            bf16 *ep=(bf16*)&e, *op=(bf16*)&o;
            #pragma unroll
            for (int j=0;j<8;j++) sBh[k2*68 + s*8 + j] = pk(ep[j],op[j]);
            uint4 e2 = *(const uint4*)(Vl + (size_t)(c*64+2*k2)*DKK + s*8);
            uint4 o2 = *(const uint4*)(Vl + (size_t)(c*64+2*k2+1)*DKK + s*8);
            bf16 *ep2=(bf16*)&e2, *op2=(bf16*)&o2;
            #pragma unroll
            for (int j=0;j<8;j++) sBl[k2*68 + s*8 + j] = pk(ep2[j],op2[j]);
        }
        __syncthreads();
        #pragma unroll
        for (int kk = 0; kk < 4; kk++){
            int kb = kk*8;
            uint32_t a_h[2][4], a_l[2][4], b_h[4][2], b_l[4][2];
            #pragma unroll
            for (int am=0;am<2;am++){
                int cm = wm*32 + am*16 + tq;
                a_h[am][0]=sAh[(kb+tr)*132+cm];   a_h[am][1]=sAh[(kb+tr)*132+cm+8];
                a_h[am][2]=sAh[(kb+tr+4)*132+cm]; a_h[am][3]=sAh[(kb+tr+4)*132+cm+8];
                a_l[am][0]=sAl[(kb+tr)*132+cm];   a_l[am][1]=sAl[(kb+tr)*132+cm+8];
                a_l[am][2]=sAl[(kb+tr+4)*132+cm]; a_l[am][3]=sAl[(kb+tr+4)*132+cm+8];
            }
            #pragma unroll
            for (int an=0;an<4;an++){
                int cn = wn*32 + an*8 + tq;
                b_h[an][0]=sBh[(kb+tr)*68+cn]; b_h[an][1]=sBh[(kb+tr+4)*68+cn];
                b_l[an][0]=sBl[(kb+tr)*68+cn]; b_l[an][1]=sBl[(kb+tr+4)*68+cn];
            }
            #pragma unroll
            for (int am=0;am<2;am++)
                #pragma unroll
                for (int an=0;an<4;an++){
                    mma16816(acc[am][an], a_h[am], b_h[an]);
                    mma16816(acc[am][an], a_h[am], b_l[an]);
                    mma16816(acc[am][an], a_l[am], b_h[an]);
                }
        }
        __syncthreads();
    }

    int b = z/HH, h = z%HH;
    #pragma unroll
    for (int am=0;am<2;am++)
    #pragma unroll
    for (int rr=0;rr<2;rr++){
        int tok = bm*128 + wm*32 + am*16 + tq + rr*8;
        #pragma unroll
        for (int an=0;an<4;an++){
            int dk = wn*32 + an*8 + tr*2;
            bf16 h0,l0,h1,l1;
            split2(acc[am][an][rr*2],h0,l0); split2(acc[am][an][rr*2+1],h1,l1);
            size_t off = ((size_t)(b*NN+tok))*DD + h*DKK + dk;
            *(uint32_t*)(g_mh+off) = pk(h0,h1);
            *(uint32_t*)(g_ml+off) = pk(l0,l1);
        }
    }
}

// ---- layernorm (proven) ----
__global__ void __launch_bounds__(256)
layernorm(const float* __restrict__ gam, const float* __restrict__ bet, float* __restrict__ out)
{
    int row = blockIdx.x, tid = threadIdx.x;
    const float* p = g_preln + (size_t)row*DD;
    float x0=p[tid], x1=p[tid+256], x2=p[tid+512];
    __shared__ float red[256];
    red[tid]=x0+x1+x2; __syncthreads();
    for (int o=128;o>0;o>>=1){ if (tid<o) red[tid]+=red[tid+o]; __syncthreads(); }
    float mu = red[0]*(1.0f/768.0f); __syncthreads();
    float d0=x0-mu, d1=x1-mu, d2=x2-mu;
    red[tid]=d0*d0+d1*d1+d2*d2; __syncthreads();
    for (int o=128;o>0;o>>=1){ if (tid<o) red[tid]+=red[tid+o]; __syncthreads(); }
    float inv = 1.0f/sqrtf(red[0]*(1.0f/768.0f)+1e-6f);
    float* o = out + (size_t)row*DD;
    o[tid]     = d0*inv*gam[tid]     + bet[tid];
    o[tid+256] = d1*inv*gam[tid+256] + bet[tid+256];
    o[tid+512] = d2*inv*gam[tid+512] + bet[tid+512];
}

extern "C" void kernel_launch(void* const* d_in, const int* in_sizes, int n_in,
                              void* d_out, int out_size)
{
    const float* x    = (const float*)d_in[0];
    const float* dist = (const float*)d_in[1];
    const float* q_w  = (const float*)d_in[2];
    const float* q_b  = (const float*)d_in[3];
    const float* k_w  = (const float*)d_in[4];
    const float* k_b  = (const float*)d_in[5];
    const float* v_w  = (const float*)d_in[6];
    const float* v_b  = (const float*)d_in[7];
    const float* s1_w = (const float*)d_in[8];
    const float* s1_b = (const float*)d_in[9];
    const float* s2_w = (const float*)d_in[10];
    const float* s2_b = (const float*)d_in[11];
    const float* ln_g = (const float*)d_in[12];
    const float* ln_b = (const float*)d_in[13];

    float* out  = (float*)d_out;
    float* attn = out + (size_t)MROWS*DD;

    cudaFuncSetAttribute(gemm_big,       cudaFuncAttributeMaxDynamicSharedMemorySize, SMEM_BIG);
    cudaFuncSetAttribute(gemm_scores_tc, cudaFuncAttributeMaxDynamicSharedMemorySize, SMEM_SC);
    cudaFuncSetAttribute(gemm_msg_tc,    cudaFuncAttributeMaxDynamicSharedMemorySize, SMEM_MSG);

    const size_t WSZ = (size_t)DD*DD;
    conv_split<<<(MROWS*DD/4+255)/256, 256>>>(x,    0, 0,     MROWS*DD/4);
    conv_split<<<(int)(WSZ/4+255)/256, 256>>>(q_w,  1, 0*WSZ, (int)(WSZ/4));
    conv_split<<<(int)(WSZ/4+255)/256, 256>>>(k_w,  1, 1*WSZ, (int)(WSZ/4));
    conv_split<<<(int)(WSZ/4+255)/256, 256>>>(v_w,  1, 2*WSZ, (int)(WSZ/4));
    conv_split<<<(int)(WSZ/4+255)/256, 256>>>(s1_w, 1, 3*WSZ, (int)(WSZ/4));
    conv_split<<<(int)(WSZ/4+255)/256, 256>>>(s2_w, 1, 4*WSZ, (int)(WSZ/4));

    build_mask<<<BB*NN, 256>>>(dist);

    gemm_big<<<dim3(DD/128, MROWS/128, 3), 256, SMEM_BIG>>>(0, 0, q_b, k_b, v_b, x, 0);
    gemm_scores_tc<<<dim3(NN/128, NN/128, BHZ), 256, SMEM_SC>>>(attn);
    softmax512<<<BHZ*NN, 128>>>(attn);
    gemm_msg_tc<<<dim3(NN/128, BHZ), 256, SMEM_MSG>>>(attn);
    gemm_big<<<dim3(DD/128, MROWS/128, 1), 256, SMEM_BIG>>>(1, 3, s1_b, s1_b, s1_b, x, 1);
    gemm_big<<<dim3(DD/128, MROWS/128, 1), 256, SMEM_BIG>>>(2, 4, s2_b, s2_b, s2_b, x, 2);
    layernorm<<<MROWS, 256>>>(ln_g, ln_b, out);
}

// round 9
// speedup vs baseline: 2.2470x; 1.4105x over previous
#include <cuda_runtime.h>
#include <cuda_bf16.h>
#include <math.h>
#include <stdint.h>

#define BB 16
#define NN 512
#define HH 12
#define DKK 64
#define DD 768
#define BHZ 192
#define MROWS 8192
#define KNN 153

typedef __nv_bfloat16 bf16;

__device__ __align__(128) bf16 g_xh[(size_t)MROWS*DD], g_xl[(size_t)MROWS*DD];
__device__ __align__(128) bf16 g_wh[(size_t)5*DD*DD],  g_wl[(size_t)5*DD*DD];
__device__ __align__(128) bf16 g_qh[(size_t)BHZ*NN*DKK], g_ql[(size_t)BHZ*NN*DKK];
__device__ __align__(128) bf16 g_kh[(size_t)BHZ*NN*DKK], g_kl[(size_t)BHZ*NN*DKK];
__device__ __align__(128) bf16 g_vh[(size_t)BHZ*NN*DKK], g_vl[(size_t)BHZ*NN*DKK];
__device__ __align__(128) bf16 g_mh[(size_t)MROWS*DD],  g_ml[(size_t)MROWS*DD];
__device__ __align__(128) bf16 g_y1h[(size_t)MROWS*DD], g_y1l[(size_t)MROWS*DD];
__device__ float g_preln[(size_t)MROWS*DD];
__device__ unsigned char g_mask[(size_t)BB*NN*NN];

__device__ __forceinline__ void split2(float v, bf16& h, bf16& l){
    h = __float2bfloat16(v); l = __float2bfloat16(v - __bfloat162float(h));
}
__device__ __forceinline__ uint32_t pk(bf16 a, bf16 b){
    uint16_t x = *(uint16_t*)&a, y = *(uint16_t*)&b;
    return (uint32_t)x | ((uint32_t)y << 16);
}
__device__ __forceinline__ void mma16816(float* c, const uint32_t* a, const uint32_t* b){
    asm volatile("mma.sync.aligned.m16n8k16.row.col.f32.bf16.bf16.f32 "
        "{%0,%1,%2,%3}, {%4,%5,%6,%7}, {%8,%9}, {%0,%1,%2,%3};"
        : "+f"(c[0]),"+f"(c[1]),"+f"(c[2]),"+f"(c[3])
        : "r"(a[0]),"r"(a[1]),"r"(a[2]),"r"(a[3]),"r"(b[0]),"r"(b[1]));
}
__device__ __forceinline__ uint32_t cvta_smem(const void* p){
    uint32_t a; asm("{ .reg .u64 t; cvta.to.shared.u64 t, %1; cvt.u32.u64 %0, t; }":"=r"(a):"l"(p)); return a;
}
__device__ __forceinline__ void cpa16(uint32_t dst, const void* src){
    asm volatile("cp.async.cg.shared.global [%0], [%1], 16;"::"r"(dst),"l"(src));
}
#define CP_COMMIT asm volatile("cp.async.commit_group;")
#define CP_WAIT0  asm volatile("cp.async.wait_group 0;")
#define CP_WAIT1  asm volatile("cp.async.wait_group 1;")

// stage 128 rows x 64 bf16 -> smem row-major, 144B row stride, via cp.async
__device__ __forceinline__ void stage_cp(uint32_t dst, const bf16* src, int row0, int k0, int ld){
    for (int i = threadIdx.x; i < 1024; i += 256){
        int r = i>>3, s = i&7;
        cpa16(dst + r*144 + s*16, src + (size_t)(row0+r)*ld + k0 + s*8);
    }
}

// ---- fp32 -> bf16 hi/lo ----
__global__ void __launch_bounds__(256)
conv_split(const float* __restrict__ src, int sel, size_t off, int n4)
{
    int i = blockIdx.x*256 + threadIdx.x;
    if (i >= n4) return;
    bf16 *hi = sel ? g_wh+off : g_xh, *lo = sel ? g_wl+off : g_xl;
    float4 v = ((const float4*)src)[i];
    bf16 h[4], l[4];
    split2(v.x,h[0],l[0]); split2(v.y,h[1],l[1]); split2(v.z,h[2],l[2]); split2(v.w,h[3],l[3]);
    ((uint2*)hi)[i] = *(uint2*)h; ((uint2*)lo)[i] = *(uint2*)l;
}

// ---- kNN mask (proven) ----
__global__ void __launch_bounds__(256)
build_mask(const float* __restrict__ dist)
{
    int b = blockIdx.x>>9, n = blockIdx.x&511, tid = threadIdx.x;
    unsigned char* mrow = g_mask + ((size_t)(b<<9)+n)*NN;
    if (n == 0){ for (int m=tid;m<NN;m+=256) mrow[m]=1; return; }
    __shared__ unsigned long long key[512];
    for (int m=tid;m<NN;m+=256){
        float v = (m==0)?0.0f:dist[(size_t)(b*511+(n-1))*511+(m-1)];
        key[m] = ((unsigned long long)__float_as_uint(v)<<32) | (unsigned)m;
    }
    __syncthreads();
    for (int k=2;k<=512;k<<=1) for (int j=k>>1;j>0;j>>=1){
        for (int i=tid;i<512;i+=256){
            int x = i^j;
            if (x>i){ bool up=((i&k)==0); unsigned long long a=key[i],c=key[x];
                if ((a>c)==up){ key[i]=c; key[x]=a; } }
        }
        __syncthreads();
    }
    for (int m=tid;m<NN;m+=256) mrow[m]=0;
    __syncthreads();
    for (int s=tid;s<KNN;s+=256) mrow[(int)(key[s]&511u)]=1;
    if (tid==0) mrow[0]=1;
}

// fragment loaders from row-major stride-36 smem
#define LOAD_A(dst, sp, cm, kb) do{ \
    (dst)[0]=(sp)[(cm)*36+(kb)+tr];     (dst)[1]=(sp)[((cm)+8)*36+(kb)+tr]; \
    (dst)[2]=(sp)[(cm)*36+(kb)+tr+4];   (dst)[3]=(sp)[((cm)+8)*36+(kb)+tr+4]; }while(0)
#define LOAD_B(dst, sp, cn, kb) do{ \
    (dst)[0]=(sp)[(cn)*36+(kb)+tr];     (dst)[1]=(sp)[(cn)*36+(kb)+tr+4]; }while(0)

// ---- big GEMM: C[128x128] = A[.x768] @ W^T + bias (cp.async double-buffered) ----
#define TILEW 4608                      // words per 128x64 tile (128*36)
#define BUFW  (4*TILEW)                 // words per buffer (Ah,Al,Bh,Bl)
#define SMEM_BIG (2*BUFW*4)             // bytes = 147456
__global__ void __launch_bounds__(256)
gemm_big(int asel, int widx0, const float* __restrict__ Bb0, const float* __restrict__ Bb1,
         const float* __restrict__ Bb2, const float* __restrict__ xres, int mode)
{
    extern __shared__ __align__(16) uint32_t sm[];
    const int bn=blockIdx.x, bm=blockIdx.y, z=blockIdx.z;
    const bf16 *Ah = asel==0?g_xh: asel==1?g_mh:g_y1h;
    const bf16 *Al = asel==0?g_xl: asel==1?g_ml:g_y1l;
    const bf16 *Wh = g_wh + (size_t)(widx0+z)*DD*DD;
    const bf16 *Wl = g_wl + (size_t)(widx0+z)*DD*DD;
    const float* Bb = z==0?Bb0 : z==1?Bb1 : Bb2;
    uint32_t sb = cvta_smem(sm);
    int tid=threadIdx.x, wid=tid>>5, lane=tid&31;
    int wm=wid&3, wn=wid>>2, tq=lane>>2, tr=lane&3;

    float acc[2][8][4];
    #pragma unroll
    for (int a=0;a<2;a++)
        #pragma unroll
        for (int b=0;b<8;b++)
            #pragma unroll
            for (int d=0;d<4;d++) acc[a][b][d]=0.0f;

    // prefetch chunk 0
    stage_cp(sb,                 Ah, bm*128, 0, DD);
    stage_cp(sb + TILEW*4,       Al, bm*128, 0, DD);
    stage_cp(sb + TILEW*8,       Wh, bn*128, 0, DD);
    stage_cp(sb + TILEW*12,      Wl, bn*128, 0, DD);
    CP_COMMIT;

    for (int c = 0; c < 12; c++){
        int buf = c & 1;
        if (c < 11){
            uint32_t nb = sb + ((c+1)&1)*(BUFW*4);
            stage_cp(nb,             Ah, bm*128, (c+1)*64, DD);
            stage_cp(nb + TILEW*4,   Al, bm*128, (c+1)*64, DD);
            stage_cp(nb + TILEW*8,   Wh, bn*128, (c+1)*64, DD);
            stage_cp(nb + TILEW*12,  Wl, bn*128, (c+1)*64, DD);
            CP_COMMIT;
            CP_WAIT1;
        } else {
            CP_WAIT0;
        }
        __syncthreads();
        const uint32_t *sAh = sm + buf*BUFW, *sAl = sAh + TILEW;
        const uint32_t *sBh = sAl + TILEW,  *sBl = sBh + TILEW;
        #pragma unroll
        for (int kk = 0; kk < 4; kk++){
            int kb = kk*8;
            uint32_t a_h[2][4], a_l[2][4], b_h[8][2], b_l[8][2];
            #pragma unroll
            for (int am=0;am<2;am++){
                int cm = wm*32 + am*16 + tq;
                LOAD_A(a_h[am], sAh, cm, kb);
                LOAD_A(a_l[am], sAl, cm, kb);
            }
            #pragma unroll
            for (int an=0;an<8;an++){
                int cn = wn*64 + an*8 + tq;
                LOAD_B(b_h[an], sBh, cn, kb);
                LOAD_B(b_l[an], sBl, cn, kb);
            }
            #pragma unroll
            for (int am=0;am<2;am++)
                #pragma unroll
                for (int an=0;an<8;an++){
                    mma16816(acc[am][an], a_h[am], b_h[an]);
                    mma16816(acc[am][an], a_h[am], b_l[an]);
                    mma16816(acc[am][an], a_l[am], b_h[an]);
                }
        }
        __syncthreads();
    }

    #pragma unroll
    for (int am=0;am<2;am++)
    #pragma unroll
    for (int rr=0;rr<2;rr++){
        int row = bm*128 + wm*32 + am*16 + tq + rr*8;
        #pragma unroll
        for (int an=0;an<8;an++){
            int col = bn*128 + wn*64 + an*8 + tr*2;
            float v0 = acc[am][an][rr*2]   + Bb[col];
            float v1 = acc[am][an][rr*2+1] + Bb[col+1];
            if (mode == 0){
                int b=row>>9, tok=row&511, h=col>>6, dk=col&63;
                size_t off = ((size_t)(b*HH+h)*NN+tok)*DKK + dk;
                bf16 h0,l0,h1,l1; split2(v0,h0,l0); split2(v1,h1,l1);
                bf16 *dh, *dl;
                if (z==0){ dh=g_qh; dl=g_ql; } else if (z==1){ dh=g_kh; dl=g_kl; }
                else { dh=g_vh; dl=g_vl; }
                *(uint32_t*)(dh+off) = pk(h0,h1);
                *(uint32_t*)(dl+off) = pk(l0,l1);
            } else if (mode == 1){
                v0 = v0/(1.0f+__expf(-v0)); v1 = v1/(1.0f+__expf(-v1));
                bf16 h0,l0,h1,l1; split2(v0,h0,l0); split2(v1,h1,l1);
                size_t off = (size_t)row*DD + col;
                *(uint32_t*)(g_y1h+off) = pk(h0,h1);
                *(uint32_t*)(g_y1l+off) = pk(l0,l1);
            } else {
                size_t off = (size_t)row*DD + col;
                float2 xr = *(const float2*)(xres+off);
                float2 o; o.x = v0+xr.x; o.y = v1+xr.y;
                *(float2*)(g_preln+off) = o;
            }
        }
    }
}

// ---- scores: S[128x128] = Q @ K^T (K=64), mask*0.125 -> attn ----
#define SMEM_SC (BUFW*4)
__global__ void __launch_bounds__(256)
gemm_scores_tc(float* __restrict__ attn)
{
    extern __shared__ __align__(16) uint32_t sm[];
    const int bn=blockIdx.x, bm=blockIdx.y, z=blockIdx.z;
    const bf16 *Qh=g_qh+(size_t)z*NN*DKK, *Ql=g_ql+(size_t)z*NN*DKK;
    const bf16 *Kh=g_kh+(size_t)z*NN*DKK, *Kl=g_kl+(size_t)z*NN*DKK;
    uint32_t sb = cvta_smem(sm);
    int tid=threadIdx.x, wid=tid>>5, lane=tid&31;
    int wm=wid&3, wn=wid>>2, tq=lane>>2, tr=lane&3;

    float acc[2][8][4];
    #pragma unroll
    for (int a=0;a<2;a++)
        #pragma unroll
        for (int b=0;b<8;b++)
            #pragma unroll
            for (int d=0;d<4;d++) acc[a][b][d]=0.0f;

    stage_cp(sb,            Qh, bm*128, 0, DKK);
    stage_cp(sb + TILEW*4,  Ql, bm*128, 0, DKK);
    stage_cp(sb + TILEW*8,  Kh, bn*128, 0, DKK);
    stage_cp(sb + TILEW*12, Kl, bn*128, 0, DKK);
    CP_COMMIT; CP_WAIT0;
    __syncthreads();

    const uint32_t *sAh = sm, *sAl = sAh + TILEW, *sBh = sAl + TILEW, *sBl = sBh + TILEW;
    #pragma unroll
    for (int kk = 0; kk < 4; kk++){
        int kb = kk*8;
        uint32_t a_h[2][4], a_l[2][4], b_h[8][2], b_l[8][2];
        #pragma unroll
        for (int am=0;am<2;am++){
            int cm = wm*32 + am*16 + tq;
            LOAD_A(a_h[am], sAh, cm, kb);
            LOAD_A(a_l[am], sAl, cm, kb);
        }
        #pragma unroll
        for (int an=0;an<8;an++){
            int cn = wn*64 + an*8 + tq;
            LOAD_B(b_h[an], sBh, cn, kb);
            LOAD_B(b_l[an], sBl, cn, kb);
        }
        #pragma unroll
        for (int am=0;am<2;am++)
            #pragma unroll
            for (int an=0;an<8;an++){
                mma16816(acc[am][an], a_h[am], b_h[an]);
                mma16816(acc[am][an], a_h[am], b_l[an]);
                mma16816(acc[am][an], a_l[am], b_h[an]);
            }
    }

    int b = z/HH;
    #pragma unroll
    for (int am=0;am<2;am++)
    #pragma unroll
    for (int rr=0;rr<2;rr++){
        int row = bm*128 + wm*32 + am*16 + tq + rr*8;
        const unsigned char* mr = g_mask + ((size_t)(b<<9)+row)*NN;
        #pragma unroll
        for (int an=0;an<8;an++){
            int col = bn*128 + wn*64 + an*8 + tr*2;
            float2 o;
            o.x = mr[col]   ? acc[am][an][rr*2]*0.125f   : -1e12f;
            o.y = mr[col+1] ? acc[am][an][rr*2+1]*0.125f : -1e12f;
            *(float2*)(attn + ((size_t)z*NN+row)*NN + col) = o;
        }
    }
}

// ---- softmax 512 ----
__global__ void __launch_bounds__(128)
softmax512(float* __restrict__ attn)
{
    float* p = attn + (size_t)blockIdx.x*NN;
    int tid = threadIdx.x;
    float v[4];
    #pragma unroll
    for (int i=0;i<4;i++) v[i]=p[tid+(i<<7)];
    float mx = fmaxf(fmaxf(v[0],v[1]),fmaxf(v[2],v[3]));
    #pragma unroll
    for (int o=16;o>0;o>>=1) mx=fmaxf(mx,__shfl_xor_sync(0xffffffffu,mx,o));
    __shared__ float smx[4], ssm[4];
    int wp=tid>>5, ln=tid&31;
    if (ln==0) smx[wp]=mx;
    __syncthreads();
    mx = fmaxf(fmaxf(smx[0],smx[1]),fmaxf(smx[2],smx[3]));
    float s=0.0f;
    #pragma unroll
    for (int i=0;i<4;i++){ v[i]=__expf(v[i]-mx); s+=v[i]; }
    #pragma unroll
    for (int o=16;o>0;o>>=1) s+=__shfl_xor_sync(0xffffffffu,s,o);
    if (ln==0) ssm[wp]=s;
    __syncthreads();
    s = ssm[0]+ssm[1]+ssm[2]+ssm[3];
    float inv = 1.0f/s;
    #pragma unroll
    for (int i=0;i<4;i++) p[tid+(i<<7)]=v[i]*inv;
}

// ---- msg = attn @ V : block 128x64, K=512 (8 chunks) — proven R8 version ----
#define SMEM_MSG ((4224*2 + 2176*2)*4)
__global__ void __launch_bounds__(256)
gemm_msg_tc(const float* __restrict__ attn)
{
    extern __shared__ uint32_t smu[];
    uint32_t *sAh=smu, *sAl=smu+4224, *sBh=smu+8448, *sBl=smu+8448+2176;
    const int bm=blockIdx.x, z=blockIdx.y;
    const float* A = attn + (size_t)z*NN*NN;
    const bf16 *Vh=g_vh+(size_t)z*NN*DKK, *Vl=g_vl+(size_t)z*NN*DKK;
    int tid=threadIdx.x, wid=tid>>5, lane=tid&31;
    int wm=wid&3, wn=wid>>2, tq=lane>>2, tr=lane&3;

    float acc[2][4][4];
    #pragma unroll
    for (int a=0;a<2;a++)
        #pragma unroll
        for (int b=0;b<4;b++)
            #pragma unroll
            for (int d=0;d<4;d++) acc[a][b][d]=0.0f;

    for (int c = 0; c < 8; c++){
        for (int i = tid; i < 1024; i += 256){
            int r = i>>3, s = i&7;
            const float* p = A + (size_t)(bm*128+r)*NN + c*64 + s*8;
            float4 f0 = ((const float4*)p)[0], f1 = ((const float4*)p)[1];
            float f[8] = {f0.x,f0.y,f0.z,f0.w,f1.x,f1.y,f1.z,f1.w};
            #pragma unroll
            for (int j=0;j<4;j++){
                bf16 h0,l0,h1,l1;
                split2(f[2*j],h0,l0); split2(f[2*j+1],h1,l1);
                sAh[(s*4+j)*132+r]=pk(h0,h1);
                sAl[(s*4+j)*132+r]=pk(l0,l1);
            }
        }
        {
            int k2 = tid>>3, s = tid&7;
            uint4 e = *(const uint4*)(Vh + (size_t)(c*64+2*k2)*DKK + s*8);
            uint4 o = *(const uint4*)(Vh + (size_t)(c*64+2*k2+1)*DKK + s*8);
            bf16 *ep=(bf16*)&e, *op=(bf16*)&o;
            #pragma unroll
            for (int j=0;j<8;j++) sBh[k2*68 + s*8 + j] = pk(ep[j],op[j]);
            uint4 e2 = *(const uint4*)(Vl + (size_t)(c*64+2*k2)*DKK + s*8);
            uint4 o2 = *(const uint4*)(Vl + (size_t)(c*64+2*k2+1)*DKK + s*8);
            bf16 *ep2=(bf16*)&e2, *op2=(bf16*)&o2;
            #pragma unroll
            for (int j=0;j<8;j++) sBl[k2*68 + s*8 + j] = pk(ep2[j],op2[j]);
        }
        __syncthreads();
        #pragma unroll
        for (int kk = 0; kk < 4; kk++){
            int kb = kk*8;
            uint32_t a_h[2][4], a_l[2][4], b_h[4][2], b_l[4][2];
            #pragma unroll
            for (int am=0;am<2;am++){
                int cm = wm*32 + am*16 + tq;
                a_h[am][0]=sAh[(kb+tr)*132+cm];   a_h[am][1]=sAh[(kb+tr)*132+cm+8];
                a_h[am][2]=sAh[(kb+tr+4)*132+cm]; a_h[am][3]=sAh[(kb+tr+4)*132+cm+8];
                a_l[am][0]=sAl[(kb+tr)*132+cm];   a_l[am][1]=sAl[(kb+tr)*132+cm+8];
                a_l[am][2]=sAl[(kb+tr+4)*132+cm]; a_l[am][3]=sAl[(kb+tr+4)*132+cm+8];
            }
            #pragma unroll
            for (int an=0;an<4;an++){
                int cn = wn*32 + an*8 + tq;
                b_h[an][0]=sBh[(kb+tr)*68+cn]; b_h[an][1]=sBh[(kb+tr+4)*68+cn];
                b_l[an][0]=sBl[(kb+tr)*68+cn]; b_l[an][1]=sBl[(kb+tr+4)*68+cn];
            }
            #pragma unroll
            for (int am=0;am<2;am++)
                #pragma unroll
                for (int an=0;an<4;an++){
                    mma16816(acc[am][an], a_h[am], b_h[an]);
                    mma16816(acc[am][an], a_h[am], b_l[an]);
                    mma16816(acc[am][an], a_l[am], b_h[an]);
                }
        }
        __syncthreads();
    }

    int b = z/HH, h = z%HH;
    #pragma unroll
    for (int am=0;am<2;am++)
    #pragma unroll
    for (int rr=0;rr<2;rr++){
        int tok = bm*128 + wm*32 + am*16 + tq + rr*8;
        #pragma unroll
        for (int an=0;an<4;an++){
            int dk = wn*32 + an*8 + tr*2;
            bf16 h0,l0,h1,l1;
            split2(acc[am][an][rr*2],h0,l0); split2(acc[am][an][rr*2+1],h1,l1);
            size_t off = ((size_t)(b*NN+tok))*DD + h*DKK + dk;
            *(uint32_t*)(g_mh+off) = pk(h0,h1);
            *(uint32_t*)(g_ml+off) = pk(l0,l1);
        }
    }
}

// ---- layernorm (proven) ----
__global__ void __launch_bounds__(256)
layernorm(const float* __restrict__ gam, const float* __restrict__ bet, float* __restrict__ out)
{
    int row = blockIdx.x, tid = threadIdx.x;
    const float* p = g_preln + (size_t)row*DD;
    float x0=p[tid], x1=p[tid+256], x2=p[tid+512];
    __shared__ float red[256];
    red[tid]=x0+x1+x2; __syncthreads();
    for (int o=128;o>0;o>>=1){ if (tid<o) red[tid]+=red[tid+o]; __syncthreads(); }
    float mu = red[0]*(1.0f/768.0f); __syncthreads();
    float d0=x0-mu, d1=x1-mu, d2=x2-mu;
    red[tid]=d0*d0+d1*d1+d2*d2; __syncthreads();
    for (int o=128;o>0;o>>=1){ if (tid<o) red[tid]+=red[tid+o]; __syncthreads(); }
    float inv = 1.0f/sqrtf(red[0]*(1.0f/768.0f)+1e-6f);
    float* o = out + (size_t)row*DD;
    o[tid]     = d0*inv*gam[tid]     + bet[tid];
    o[tid+256] = d1*inv*gam[tid+256] + bet[tid+256];
    o[tid+512] = d2*inv*gam[tid+512] + bet[tid+512];
}

extern "C" void kernel_launch(void* const* d_in, const int* in_sizes, int n_in,
                              void* d_out, int out_size)
{
    const float* x    = (const float*)d_in[0];
    const float* dist = (const float*)d_in[1];
    const float* q_w  = (const float*)d_in[2];
    const float* q_b  = (const float*)d_in[3];
    const float* k_w  = (const float*)d_in[4];
    const float* k_b  = (const float*)d_in[5];
    const float* v_w  = (const float*)d_in[6];
    const float* v_b  = (const float*)d_in[7];
    const float* s1_w = (const float*)d_in[8];
    const float* s1_b = (const float*)d_in[9];
    const float* s2_w = (const float*)d_in[10];
    const float* s2_b = (const float*)d_in[11];
    const float* ln_g = (const float*)d_in[12];
    const float* ln_b = (const float*)d_in[13];

    float* out  = (float*)d_out;
    float* attn = out + (size_t)MROWS*DD;

    cudaFuncSetAttribute(gemm_big,       cudaFuncAttributeMaxDynamicSharedMemorySize, SMEM_BIG);
    cudaFuncSetAttribute(gemm_scores_tc, cudaFuncAttributeMaxDynamicSharedMemorySize, SMEM_SC);
    cudaFuncSetAttribute(gemm_msg_tc,    cudaFuncAttributeMaxDynamicSharedMemorySize, SMEM_MSG);

    const size_t WSZ = (size_t)DD*DD;
    conv_split<<<(MROWS*DD/4+255)/256, 256>>>(x,    0, 0,     MROWS*DD/4);
    conv_split<<<(int)(WSZ/4+255)/256, 256>>>(q_w,  1, 0*WSZ, (int)(WSZ/4));
    conv_split<<<(int)(WSZ/4+255)/256, 256>>>(k_w,  1, 1*WSZ, (int)(WSZ/4));
    conv_split<<<(int)(WSZ/4+255)/256, 256>>>(v_w,  1, 2*WSZ, (int)(WSZ/4));
    conv_split<<<(int)(WSZ/4+255)/256, 256>>>(s1_w, 1, 3*WSZ, (int)(WSZ/4));
    conv_split<<<(int)(WSZ/4+255)/256, 256>>>(s2_w, 1, 4*WSZ, (int)(WSZ/4));

    build_mask<<<BB*NN, 256>>>(dist);

    gemm_big<<<dim3(DD/128, MROWS/128, 3), 256, SMEM_BIG>>>(0, 0, q_b, k_b, v_b, x, 0);
    gemm_scores_tc<<<dim3(NN/128, NN/128, BHZ), 256, SMEM_SC>>>(attn);
    softmax512<<<BHZ*NN, 128>>>(attn);
    gemm_msg_tc<<<dim3(NN/128, BHZ), 256, SMEM_MSG>>>(attn);
    gemm_big<<<dim3(DD/128, MROWS/128, 1), 256, SMEM_BIG>>>(1, 3, s1_b, s1_b, s1_b, x, 1);
    gemm_big<<<dim3(DD/128, MROWS/128, 1), 256, SMEM_BIG>>>(2, 4, s2_b, s2_b, s2_b, x, 2);
    layernorm<<<MROWS, 256>>>(ln_g, ln_b, out);
}

// round 10
// speedup vs baseline: 2.9240x; 1.3013x over previous
#include <cuda_runtime.h>
#include <cuda_fp16.h>
#include <math.h>
#include <stdint.h>

#define BB 16
#define NN 512
#define HH 12
#define DKK 64
#define DD 768
#define BHZ 192
#define MROWS 8192
#define KNN 153

typedef __half f16;

// activations split hi/lo (A operands); weights / K / V hi-only (B operands)
__device__ __align__(128) f16 g_xh[(size_t)MROWS*DD], g_xl[(size_t)MROWS*DD];
__device__ __align__(128) f16 g_w [(size_t)5*DD*DD];
__device__ __align__(128) f16 g_qh[(size_t)BHZ*NN*DKK], g_ql[(size_t)BHZ*NN*DKK];
__device__ __align__(128) f16 g_k [(size_t)BHZ*NN*DKK];
__device__ __align__(128) f16 g_vt[(size_t)BHZ*DKK*NN];          // V transposed [z][dk][tok]
__device__ __align__(128) f16 g_mh[(size_t)MROWS*DD],  g_ml[(size_t)MROWS*DD];
__device__ __align__(128) f16 g_y1h[(size_t)MROWS*DD], g_y1l[(size_t)MROWS*DD];
__device__ __align__(128) f16 g_ph[(size_t)BHZ*NN*NN], g_pl[(size_t)BHZ*NN*NN]; // attn split
__device__ float g_preln[(size_t)MROWS*DD];
__device__ unsigned char g_mask[(size_t)BB*NN*NN];

__device__ __forceinline__ void split2(float v, f16& h, f16& l){
    h = __float2half_rn(v); l = __float2half_rn(v - __half2float(h));
}
__device__ __forceinline__ uint32_t pk(f16 a, f16 b){
    uint16_t x = *(uint16_t*)&a, y = *(uint16_t*)&b;
    return (uint32_t)x | ((uint32_t)y << 16);
}
__device__ __forceinline__ void mma16816(float* c, const uint32_t* a, const uint32_t* b){
    asm volatile("mma.sync.aligned.m16n8k16.row.col.f32.f16.f16.f32 "
        "{%0,%1,%2,%3}, {%4,%5,%6,%7}, {%8,%9}, {%0,%1,%2,%3};"
        : "+f"(c[0]),"+f"(c[1]),"+f"(c[2]),"+f"(c[3])
        : "r"(a[0]),"r"(a[1]),"r"(a[2]),"r"(a[3]),"r"(b[0]),"r"(b[1]));
}
__device__ __forceinline__ uint32_t cvta_smem(const void* p){
    uint32_t a; asm("{ .reg .u64 t; cvta.to.shared.u64 t, %1; cvt.u32.u64 %0, t; }":"=r"(a):"l"(p)); return a;
}
__device__ __forceinline__ void cpa16(uint32_t dst, const void* src){
    asm volatile("cp.async.cg.shared.global [%0], [%1], 16;"::"r"(dst),"l"(src));
}
#define CP_COMMIT asm volatile("cp.async.commit_group;")
#define CP_WAIT0  asm volatile("cp.async.wait_group 0;")
#define CP_WAIT1  asm volatile("cp.async.wait_group 1;")

// stage nrows x 64 f16 -> smem row-major, 144B row stride
__device__ __forceinline__ void stage_cp(uint32_t dst, const f16* src, int row0, int k0, int ld, int nrows){
    for (int i = threadIdx.x; i < nrows*8; i += 256){
        int r = i>>3, s = i&7;
        cpa16(dst + r*144 + s*16, src + (size_t)(row0+r)*ld + k0 + s*8);
    }
}

// fragment loaders from row-major stride-36 smem
#define LOAD_A(dst, sp, cm, kb) do{ \
    (dst)[0]=(sp)[(cm)*36+(kb)+tr];     (dst)[1]=(sp)[((cm)+8)*36+(kb)+tr]; \
    (dst)[2]=(sp)[(cm)*36+(kb)+tr+4];   (dst)[3]=(sp)[((cm)+8)*36+(kb)+tr+4]; }while(0)
#define LOAD_B(dst, sp, cn, kb) do{ \
    (dst)[0]=(sp)[(cn)*36+(kb)+tr];     (dst)[1]=(sp)[(cn)*36+(kb)+tr+4]; }while(0)

// ---- fp32 -> fp16 hi/lo (x) ----
__global__ void __launch_bounds__(256)
conv_split_x(const float* __restrict__ src, int n4)
{
    int i = blockIdx.x*256 + threadIdx.x;
    if (i >= n4) return;
    float4 v = ((const float4*)src)[i];
    f16 h[4], l[4];
    split2(v.x,h[0],l[0]); split2(v.y,h[1],l[1]); split2(v.z,h[2],l[2]); split2(v.w,h[3],l[3]);
    ((uint2*)g_xh)[i] = *(uint2*)h; ((uint2*)g_xl)[i] = *(uint2*)l;
}
// ---- fp32 -> fp16 hi only (weights) ----
__global__ void __launch_bounds__(256)
conv_h(const float* __restrict__ src, size_t off, int n4)
{
    int i = blockIdx.x*256 + threadIdx.x;
    if (i >= n4) return;
    float4 v = ((const float4*)src)[i];
    f16 h[4];
    h[0]=__float2half_rn(v.x); h[1]=__float2half_rn(v.y);
    h[2]=__float2half_rn(v.z); h[3]=__float2half_rn(v.w);
    ((uint2*)(g_w+off))[i] = *(uint2*)h;
}

// ---- kNN mask (proven) ----
__global__ void __launch_bounds__(256)
build_mask(const float* __restrict__ dist)
{
    int b = blockIdx.x>>9, n = blockIdx.x&511, tid = threadIdx.x;
    unsigned char* mrow = g_mask + ((size_t)(b<<9)+n)*NN;
    if (n == 0){ for (int m=tid;m<NN;m+=256) mrow[m]=1; return; }
    __shared__ unsigned long long key[512];
    for (int m=tid;m<NN;m+=256){
        float v = (m==0)?0.0f:dist[(size_t)(b*511+(n-1))*511+(m-1)];
        key[m] = ((unsigned long long)__float_as_uint(v)<<32) | (unsigned)m;
    }
    __syncthreads();
    for (int k=2;k<=512;k<<=1) for (int j=k>>1;j>0;j>>=1){
        for (int i=tid;i<512;i+=256){
            int x = i^j;
            if (x>i){ bool up=((i&k)==0); unsigned long long a=key[i],c=key[x];
                if ((a>c)==up){ key[i]=c; key[x]=a; } }
        }
        __syncthreads();
    }
    for (int m=tid;m<NN;m+=256) mrow[m]=0;
    __syncthreads();
    for (int s=tid;s<KNN;s+=256) mrow[(int)(key[s]&511u)]=1;
    if (tid==0) mrow[0]=1;
}

// ---- big GEMM: C[128x128] = A @ W^T + bias, fp16 2-term, cp.async dbuf ----
#define TILEW 4608                       // words per 128x64 tile
#define BUFW  (3*TILEW)                  // Ah, Al, Bh
#define SMEM_BIG (2*BUFW*4)              // 110592 B
__global__ void __launch_bounds__(256)
gemm_big(int asel, int widx0, const float* __restrict__ Bb0, const float* __restrict__ Bb1,
         const float* __restrict__ Bb2, const float* __restrict__ xres, int mode)
{
    extern __shared__ __align__(16) uint32_t sm[];
    const int bn=blockIdx.x, bm=blockIdx.y, z=blockIdx.z;
    const f16 *Ah = asel==0?g_xh: asel==1?g_mh:g_y1h;
    const f16 *Al = asel==0?g_xl: asel==1?g_ml:g_y1l;
    const f16 *Wh = g_w + (size_t)(widx0+z)*DD*DD;
    const float* Bb = z==0?Bb0 : z==1?Bb1 : Bb2;
    uint32_t sb = cvta_smem(sm);
    int tid=threadIdx.x, wid=tid>>5, lane=tid&31;
    int wm=wid&3, wn=wid>>2, tq=lane>>2, tr=lane&3;

    float acc[2][8][4];
    #pragma unroll
    for (int a=0;a<2;a++)
        #pragma unroll
        for (int b=0;b<8;b++)
            #pragma unroll
            for (int d=0;d<4;d++) acc[a][b][d]=0.0f;

    stage_cp(sb,             Ah, bm*128, 0, DD, 128);
    stage_cp(sb + TILEW*4,   Al, bm*128, 0, DD, 128);
    stage_cp(sb + TILEW*8,   Wh, bn*128, 0, DD, 128);
    CP_COMMIT;

    for (int c = 0; c < 12; c++){
        int buf = c & 1;
        if (c < 11){
            uint32_t nb = sb + ((c+1)&1)*(BUFW*4);
            stage_cp(nb,            Ah, bm*128, (c+1)*64, DD, 128);
            stage_cp(nb + TILEW*4,  Al, bm*128, (c+1)*64, DD, 128);
            stage_cp(nb + TILEW*8,  Wh, bn*128, (c+1)*64, DD, 128);
            CP_COMMIT;
            CP_WAIT1;
        } else {
            CP_WAIT0;
        }
        __syncthreads();
        const uint32_t *sAh = sm + buf*BUFW, *sAl = sAh + TILEW, *sBh = sAl + TILEW;
        #pragma unroll
        for (int kk = 0; kk < 4; kk++){
            int kb = kk*8;
            uint32_t a_h[2][4], a_l[2][4], b_h[8][2];
            #pragma unroll
            for (int am=0;am<2;am++){
                int cm = wm*32 + am*16 + tq;
                LOAD_A(a_h[am], sAh, cm, kb);
                LOAD_A(a_l[am], sAl, cm, kb);
            }
            #pragma unroll
            for (int an=0;an<8;an++){
                int cn = wn*64 + an*8 + tq;
                LOAD_B(b_h[an], sBh, cn, kb);
            }
            #pragma unroll
            for (int am=0;am<2;am++)
                #pragma unroll
                for (int an=0;an<8;an++){
                    mma16816(acc[am][an], a_h[am], b_h[an]);
                    mma16816(acc[am][an], a_l[am], b_h[an]);
                }
        }
        __syncthreads();
    }

    #pragma unroll
    for (int am=0;am<2;am++)
    #pragma unroll
    for (int rr=0;rr<2;rr++){
        int row = bm*128 + wm*32 + am*16 + tq + rr*8;
        #pragma unroll
        for (int an=0;an<8;an++){
            int col = bn*128 + wn*64 + an*8 + tr*2;
            float v0 = acc[am][an][rr*2]   + Bb[col];
            float v1 = acc[am][an][rr*2+1] + Bb[col+1];
            if (mode == 0){
                int b=row>>9, tok=row&511, h=col>>6, dk=col&63;
                if (z==0){
                    size_t off = ((size_t)(b*HH+h)*NN+tok)*DKK + dk;
                    f16 h0,l0,h1,l1; split2(v0,h0,l0); split2(v1,h1,l1);
                    *(uint32_t*)(g_qh+off) = pk(h0,h1);
                    *(uint32_t*)(g_ql+off) = pk(l0,l1);
                } else if (z==1){
                    size_t off = ((size_t)(b*HH+h)*NN+tok)*DKK + dk;
                    *(uint32_t*)(g_k+off) = pk(__float2half_rn(v0),__float2half_rn(v1));
                } else {
                    size_t base = ((size_t)(b*HH+h)*DKK + dk)*NN + tok;
                    g_vt[base]      = __float2half_rn(v0);
                    g_vt[base + NN] = __float2half_rn(v1);
                }
            } else if (mode == 1){
                v0 = v0/(1.0f+__expf(-v0)); v1 = v1/(1.0f+__expf(-v1));
                f16 h0,l0,h1,l1; split2(v0,h0,l0); split2(v1,h1,l1);
                size_t off = (size_t)row*DD + col;
                *(uint32_t*)(g_y1h+off) = pk(h0,h1);
                *(uint32_t*)(g_y1l+off) = pk(l0,l1);
            } else {
                size_t off = (size_t)row*DD + col;
                float2 xr = *(const float2*)(xres+off);
                float2 o; o.x = v0+xr.x; o.y = v1+xr.y;
                *(float2*)(g_preln+off) = o;
            }
        }
    }
}

// ---- scores: S[128x128] = Q @ K^T (K=64), mask*0.125 -> attn ----
#define SMEM_SC (BUFW*4)
__global__ void __launch_bounds__(256)
gemm_scores_tc(float* __restrict__ attn)
{
    extern __shared__ __align__(16) uint32_t sm[];
    const int bn=blockIdx.x, bm=blockIdx.y, z=blockIdx.z;
    const f16 *Qh=g_qh+(size_t)z*NN*DKK, *Ql=g_ql+(size_t)z*NN*DKK;
    const f16 *Kh=g_k +(size_t)z*NN*DKK;
    uint32_t sb = cvta_smem(sm);
    int tid=threadIdx.x, wid=tid>>5, lane=tid&31;
    int wm=wid&3, wn=wid>>2, tq=lane>>2, tr=lane&3;

    float acc[2][8][4];
    #pragma unroll
    for (int a=0;a<2;a++)
        #pragma unroll
        for (int b=0;b<8;b++)
            #pragma unroll
            for (int d=0;d<4;d++) acc[a][b][d]=0.0f;

    stage_cp(sb,            Qh, bm*128, 0, DKK, 128);
    stage_cp(sb + TILEW*4,  Ql, bm*128, 0, DKK, 128);
    stage_cp(sb + TILEW*8,  Kh, bn*128, 0, DKK, 128);
    CP_COMMIT; CP_WAIT0;
    __syncthreads();

    const uint32_t *sAh = sm, *sAl = sAh + TILEW, *sBh = sAl + TILEW;
    #pragma unroll
    for (int kk = 0; kk < 4; kk++){
        int kb = kk*8;
        uint32_t a_h[2][4], a_l[2][4], b_h[8][2];
        #pragma unroll
        for (int am=0;am<2;am++){
            int cm = wm*32 + am*16 + tq;
            LOAD_A(a_h[am], sAh, cm, kb);
            LOAD_A(a_l[am], sAl, cm, kb);
        }
        #pragma unroll
        for (int an=0;an<8;an++){
            int cn = wn*64 + an*8 + tq;
            LOAD_B(b_h[an], sBh, cn, kb);
        }
        #pragma unroll
        for (int am=0;am<2;am++)
            #pragma unroll
            for (int an=0;an<8;an++){
                mma16816(acc[am][an], a_h[am], b_h[an]);
                mma16816(acc[am][an], a_l[am], b_h[an]);
            }
    }

    int b = z/HH;
    #pragma unroll
    for (int am=0;am<2;am++)
    #pragma unroll
    for (int rr=0;rr<2;rr++){
        int row = bm*128 + wm*32 + am*16 + tq + rr*8;
        const unsigned char* mr = g_mask + ((size_t)(b<<9)+row)*NN;
        #pragma unroll
        for (int an=0;an<8;an++){
            int col = bn*128 + wn*64 + an*8 + tr*2;
            float2 o;
            o.x = mr[col]   ? acc[am][an][rr*2]*0.125f   : -1e12f;
            o.y = mr[col+1] ? acc[am][an][rr*2+1]*0.125f : -1e12f;
            *(float2*)(attn + ((size_t)z*NN+row)*NN + col) = o;
        }
    }
}

// ---- softmax 512: normalize attn in place + emit fp16 hi/lo split ----
__global__ void __launch_bounds__(128)
softmax512(float* __restrict__ attn)
{
    size_t rb = (size_t)blockIdx.x*NN;
    float* p = attn + rb;
    int tid = threadIdx.x;
    float v[4];
    #pragma unroll
    for (int i=0;i<4;i++) v[i]=p[tid+(i<<7)];
    float mx = fmaxf(fmaxf(v[0],v[1]),fmaxf(v[2],v[3]));
    #pragma unroll
    for (int o=16;o>0;o>>=1) mx=fmaxf(mx,__shfl_xor_sync(0xffffffffu,mx,o));
    __shared__ float smx[4], ssm[4];
    int wp=tid>>5, ln=tid&31;
    if (ln==0) smx[wp]=mx;
    __syncthreads();
    mx = fmaxf(fmaxf(smx[0],smx[1]),fmaxf(smx[2],smx[3]));
    float s=0.0f;
    #pragma unroll
    for (int i=0;i<4;i++){ v[i]=__expf(v[i]-mx); s+=v[i]; }
    #pragma unroll
    for (int o=16;o>0;o>>=1) s+=__shfl_xor_sync(0xffffffffu,s,o);
    if (ln==0) ssm[wp]=s;
    __syncthreads();
    s = ssm[0]+ssm[1]+ssm[2]+ssm[3];
    float inv = 1.0f/s;
    #pragma unroll
    for (int i=0;i<4;i++){
        float val = v[i]*inv;
        int idx = tid+(i<<7);
        p[idx] = val;
        f16 hh, hl; split2(val, hh, hl);
        g_ph[rb+idx] = hh;
        g_pl[rb+idx] = hl;
    }
}

// ---- msg = attn @ V : 128x64 tile, K=512, cp.async dbuf, fp16 2-term ----
#define BTILEW 2304                       // 64 rows * 36 words
#define MBUFW (2*TILEW + BTILEW)          // Ah, Al, Bh
#define SMEM_MSG (2*MBUFW*4)              // 92160 B
__global__ void __launch_bounds__(256)
gemm_msg_tc(void)
{
    extern __shared__ __align__(16) uint32_t sm[];
    const int bm=blockIdx.x, z=blockIdx.y;
    const f16 *Ahp = g_ph + (size_t)z*NN*NN;
    const f16 *Alp = g_pl + (size_t)z*NN*NN;
    const f16 *Vt  = g_vt + (size_t)z*DKK*NN;
    uint32_t sb = cvta_smem(sm);
    int tid=threadIdx.x, wid=tid>>5, lane=tid&31;
    int wm=wid&3, wn=wid>>2, tq=lane>>2, tr=lane&3;

    float acc[2][4][4];
    #pragma unroll
    for (int a=0;a<2;a++)
        #pragma unroll
        for (int b=0;b<4;b++)
            #pragma unroll
            for (int d=0;d<4;d++) acc[a][b][d]=0.0f;

    stage_cp(sb,            Ahp, bm*128, 0, NN, 128);
    stage_cp(sb + TILEW*4,  Alp, bm*128, 0, NN, 128);
    stage_cp(sb + TILEW*8,  Vt,  0,      0, NN, 64);
    CP_COMMIT;

    for (int c = 0; c < 8; c++){
        int buf = c & 1;
        if (c < 7){
            uint32_t nb = sb + ((c+1)&1)*(MBUFW*4);
            stage_cp(nb,            Ahp, bm*128, (c+1)*64, NN, 128);
            stage_cp(nb + TILEW*4,  Alp, bm*128, (c+1)*64, NN, 128);
            stage_cp(nb + TILEW*8,  Vt,  0,      (c+1)*64, NN, 64);
            CP_COMMIT;
            CP_WAIT1;
        } else {
            CP_WAIT0;
        }
        __syncthreads();
        const uint32_t *sAh = sm + buf*MBUFW, *sAl = sAh + TILEW, *sBh = sAl + TILEW;
        #pragma unroll
        for (int kk = 0; kk < 4; kk++){
            int kb = kk*8;
            uint32_t a_h[2][4], a_l[2][4], b_h[4][2];
            #pragma unroll
            for (int am=0;am<2;am++){
                int cm = wm*32 + am*16 + tq;
                LOAD_A(a_h[am], sAh, cm, kb);
                LOAD_A(a_l[am], sAl, cm, kb);
            }
            #pragma unroll
            for (int an=0;an<4;an++){
                int cn = wn*32 + an*8 + tq;
                LOAD_B(b_h[an], sBh, cn, kb);
            }
            #pragma unroll
            for (int am=0;am<2;am++)
                #pragma unroll
                for (int an=0;an<4;an++){
                    mma16816(acc[am][an], a_h[am], b_h[an]);
                    mma16816(acc[am][an], a_l[am], b_h[an]);
                }
        }
        __syncthreads();
    }

    int b = z/HH, h = z%HH;
    #pragma unroll
    for (int am=0;am<2;am++)
    #pragma unroll
    for (int rr=0;rr<2;rr++){
        int tok = bm*128 + wm*32 + am*16 + tq + rr*8;
        #pragma unroll
        for (int an=0;an<4;an++){
            int dk = wn*32 + an*8 + tr*2;
            f16 h0,l0,h1,l1;
            split2(acc[am][an][rr*2],h0,l0); split2(acc[am][an][rr*2+1],h1,l1);
            size_t off = ((size_t)(b*NN+tok))*DD + h*DKK + dk;
            *(uint32_t*)(g_mh+off) = pk(h0,h1);
            *(uint32_t*)(g_ml+off) = pk(l0,l1);
        }
    }
}

// ---- layernorm (proven) ----
__global__ void __launch_bounds__(256)
layernorm(const float* __restrict__ gam, const float* __restrict__ bet, float* __restrict__ out)
{
    int row = blockIdx.x, tid = threadIdx.x;
    const float* p = g_preln + (size_t)row*DD;
    float x0=p[tid], x1=p[tid+256], x2=p[tid+512];
    __shared__ float red[256];
    red[tid]=x0+x1+x2; __syncthreads();
    for (int o=128;o>0;o>>=1){ if (tid<o) red[tid]+=red[tid+o]; __syncthreads(); }
    float mu = red[0]*(1.0f/768.0f); __syncthreads();
    float d0=x0-mu, d1=x1-mu, d2=x2-mu;
    red[tid]=d0*d0+d1*d1+d2*d2; __syncthreads();
    for (int o=128;o>0;o>>=1){ if (tid<o) red[tid]+=red[tid+o]; __syncthreads(); }
    float inv = 1.0f/sqrtf(red[0]*(1.0f/768.0f)+1e-6f);
    float* o = out + (size_t)row*DD;
    o[tid]     = d0*inv*gam[tid]     + bet[tid];
    o[tid+256] = d1*inv*gam[tid+256] + bet[tid+256];
    o[tid+512] = d2*inv*gam[tid+512] + bet[tid+512];
}

extern "C" void kernel_launch(void* const* d_in, const int* in_sizes, int n_in,
                              void* d_out, int out_size)
{
    const float* x    = (const float*)d_in[0];
    const float* dist = (const float*)d_in[1];
    const float* q_w  = (const float*)d_in[2];
    const float* q_b  = (const float*)d_in[3];
    const float* k_w  = (const float*)d_in[4];
    const float* k_b  = (const float*)d_in[5];
    const float* v_w  = (const float*)d_in[6];
    const float* v_b  = (const float*)d_in[7];
    const float* s1_w = (const float*)d_in[8];
    const float* s1_b = (const float*)d_in[9];
    const float* s2_w = (const float*)d_in[10];
    const float* s2_b = (const float*)d_in[11];
    const float* ln_g = (const float*)d_in[12];
    const float* ln_b = (const float*)d_in[13];

    float* out  = (float*)d_out;
    float* attn = out + (size_t)MROWS*DD;

    cudaFuncSetAttribute(gemm_big,       cudaFuncAttributeMaxDynamicSharedMemorySize, SMEM_BIG);
    cudaFuncSetAttribute(gemm_scores_tc, cudaFuncAttributeMaxDynamicSharedMemorySize, SMEM_SC);
    cudaFuncSetAttribute(gemm_msg_tc,    cudaFuncAttributeMaxDynamicSharedMemorySize, SMEM_MSG);

    const size_t WSZ = (size_t)DD*DD;
    conv_split_x<<<(MROWS*DD/4+255)/256, 256>>>(x, MROWS*DD/4);
    conv_h<<<(int)(WSZ/4+255)/256, 256>>>(q_w,  0*WSZ, (int)(WSZ/4));
    conv_h<<<(int)(WSZ/4+255)/256, 256>>>(k_w,  1*WSZ, (int)(WSZ/4));
    conv_h<<<(int)(WSZ/4+255)/256, 256>>>(v_w,  2*WSZ, (int)(WSZ/4));
    conv_h<<<(int)(WSZ/4+255)/256, 256>>>(s1_w, 3*WSZ, (int)(WSZ/4));
    conv_h<<<(int)(WSZ/4+255)/256, 256>>>(s2_w, 4*WSZ, (int)(WSZ/4));

    build_mask<<<BB*NN, 256>>>(dist);

    gemm_big<<<dim3(DD/128, MROWS/128, 3), 256, SMEM_BIG>>>(0, 0, q_b, k_b, v_b, x, 0);
    gemm_scores_tc<<<dim3(NN/128, NN/128, BHZ), 256, SMEM_SC>>>(attn);
    softmax512<<<BHZ*NN, 128>>>(attn);
    gemm_msg_tc<<<dim3(NN/128, BHZ), 256, SMEM_MSG>>>();
    gemm_big<<<dim3(DD/128, MROWS/128, 1), 256, SMEM_BIG>>>(1, 3, s1_b, s1_b, s1_b, x, 1);
    gemm_big<<<dim3(DD/128, MROWS/128, 1), 256, SMEM_BIG>>>(2, 4, s2_b, s2_b, s2_b, x, 2);
    layernorm<<<MROWS, 256>>>(ln_g, ln_b, out);
}

// round 11
// speedup vs baseline: 2.9723x; 1.0165x over previous
#include <cuda_runtime.h>
#include <cuda_fp16.h>
#include <math.h>
#include <stdint.h>

#define BB 16
#define NN 512
#define HH 12
#define DKK 64
#define DD 768
#define BHZ 192
#define MROWS 8192
#define KNN 153

typedef __half f16;

__device__ __align__(128) f16 g_xh[(size_t)MROWS*DD], g_xl[(size_t)MROWS*DD];
__device__ __align__(128) f16 g_w [(size_t)5*DD*DD];
__device__ __align__(128) f16 g_qh[(size_t)BHZ*NN*DKK], g_ql[(size_t)BHZ*NN*DKK];
__device__ __align__(128) f16 g_k [(size_t)BHZ*NN*DKK];
__device__ __align__(128) f16 g_vt[(size_t)BHZ*DKK*NN];
__device__ __align__(128) f16 g_mh[(size_t)MROWS*DD],  g_ml[(size_t)MROWS*DD];
__device__ __align__(128) f16 g_y1h[(size_t)MROWS*DD], g_y1l[(size_t)MROWS*DD];
__device__ __align__(128) f16 g_ph[(size_t)BHZ*NN*NN], g_pl[(size_t)BHZ*NN*NN];
__device__ float g_preln[(size_t)MROWS*DD];
__device__ unsigned char g_mask[(size_t)BB*NN*NN];

__device__ __forceinline__ void split2(float v, f16& h, f16& l){
    h = __float2half_rn(v); l = __float2half_rn(v - __half2float(h));
}
__device__ __forceinline__ uint32_t pk(f16 a, f16 b){
    uint16_t x = *(uint16_t*)&a, y = *(uint16_t*)&b;
    return (uint32_t)x | ((uint32_t)y << 16);
}
__device__ __forceinline__ void mma16816(float* c, const uint32_t* a, const uint32_t* b){
    asm volatile("mma.sync.aligned.m16n8k16.row.col.f32.f16.f16.f32 "
        "{%0,%1,%2,%3}, {%4,%5,%6,%7}, {%8,%9}, {%0,%1,%2,%3};"
        : "+f"(c[0]),"+f"(c[1]),"+f"(c[2]),"+f"(c[3])
        : "r"(a[0]),"r"(a[1]),"r"(a[2]),"r"(a[3]),"r"(b[0]),"r"(b[1]));
}
__device__ __forceinline__ void ldsm4(uint32_t* r, uint32_t addr){
    asm volatile("ldmatrix.sync.aligned.m8n8.x4.shared.b16 {%0,%1,%2,%3}, [%4];"
        : "=r"(r[0]),"=r"(r[1]),"=r"(r[2]),"=r"(r[3]) : "r"(addr));
}
__device__ __forceinline__ uint32_t cvta_smem(const void* p){
    uint32_t a; asm("{ .reg .u64 t; cvta.to.shared.u64 t, %1; cvt.u32.u64 %0, t; }":"=r"(a):"l"(p)); return a;
}
__device__ __forceinline__ void cpa16(uint32_t dst, const void* src){
    asm volatile("cp.async.cg.shared.global [%0], [%1], 16;"::"r"(dst),"l"(src));
}
#define CP_COMMIT asm volatile("cp.async.commit_group;")
#define CP_WAIT0  asm volatile("cp.async.wait_group 0;")
#define CP_WAIT1  asm volatile("cp.async.wait_group 1;")

// stage nrows x 64 f16 -> smem row-major, 144B row stride
__device__ __forceinline__ void stage_cp(uint32_t dst, const f16* src, int row0, int k0, int ld, int nrows){
    for (int i = threadIdx.x; i < nrows*8; i += 256){
        int r = i>>3, s = i&7;
        cpa16(dst + r*144 + s*16, src + (size_t)(row0+r)*ld + k0 + s*8);
    }
}

// ldmatrix per-lane byte offsets within a tile (stride 36 words = 144 B)
// A fragment (m16k16), fragment base row mrow0:
//   lane: row = mrow0 + (lane&7) + ((lane>>3)&1)*8 ; kword = (lane>>4)*4
// B fragment pair (two n8k16 at nrow0, nrow0+8):
//   lane: row = nrow0 + (lane&7) + ((lane>>4)&1)*8 ; kword = ((lane>>3)&1)*4
__device__ __forceinline__ int a_ldsm_off(int mrow0, int lane){
    return ((mrow0 + (lane&7) + ((lane>>3)&1)*8)*36 + (lane>>4)*4)*4;
}
__device__ __forceinline__ int b_ldsm_off(int nrow0, int lane){
    return ((nrow0 + (lane&7) + ((lane>>4)&1)*8)*36 + ((lane>>3)&1)*4)*4;
}

// ---- fp32 -> fp16 hi/lo (x) ----
__global__ void __launch_bounds__(256)
conv_split_x(const float* __restrict__ src, int n4)
{
    int i = blockIdx.x*256 + threadIdx.x;
    if (i >= n4) return;
    float4 v = ((const float4*)src)[i];
    f16 h[4], l[4];
    split2(v.x,h[0],l[0]); split2(v.y,h[1],l[1]); split2(v.z,h[2],l[2]); split2(v.w,h[3],l[3]);
    ((uint2*)g_xh)[i] = *(uint2*)h; ((uint2*)g_xl)[i] = *(uint2*)l;
}
// ---- fp32 -> fp16 hi only (weights) ----
__global__ void __launch_bounds__(256)
conv_h(const float* __restrict__ src, size_t off, int n4)
{
    int i = blockIdx.x*256 + threadIdx.x;
    if (i >= n4) return;
    float4 v = ((const float4*)src)[i];
    f16 h[4];
    h[0]=__float2half_rn(v.x); h[1]=__float2half_rn(v.y);
    h[2]=__float2half_rn(v.z); h[3]=__float2half_rn(v.w);
    ((uint2*)(g_w+off))[i] = *(uint2*)h;
}

// ---- kNN mask (proven) ----
__global__ void __launch_bounds__(256)
build_mask(const float* __restrict__ dist)
{
    int b = blockIdx.x>>9, n = blockIdx.x&511, tid = threadIdx.x;
    unsigned char* mrow = g_mask + ((size_t)(b<<9)+n)*NN;
    if (n == 0){ for (int m=tid;m<NN;m+=256) mrow[m]=1; return; }
    __shared__ unsigned long long key[512];
    for (int m=tid;m<NN;m+=256){
        float v = (m==0)?0.0f:dist[(size_t)(b*511+(n-1))*511+(m-1)];
        key[m] = ((unsigned long long)__float_as_uint(v)<<32) | (unsigned)m;
    }
    __syncthreads();
    for (int k=2;k<=512;k<<=1) for (int j=k>>1;j>0;j>>=1){
        for (int i=tid;i<512;i+=256){
            int x = i^j;
            if (x>i){ bool up=((i&k)==0); unsigned long long a=key[i],c=key[x];
                if ((a>c)==up){ key[i]=c; key[x]=a; } }
        }
        __syncthreads();
    }
    for (int m=tid;m<NN;m+=256) mrow[m]=0;
    __syncthreads();
    for (int s=tid;s<KNN;s+=256) mrow[(int)(key[s]&511u)]=1;
    if (tid==0) mrow[0]=1;
}

// ---- big GEMM: C[128x128] = A @ W^T + bias, fp16 2-term, ldmatrix + cp.async dbuf ----
#define TILEW 4608
#define BUFW  (3*TILEW)
#define SMEM_BIG (2*BUFW*4)
__global__ void __launch_bounds__(256)
gemm_big(int asel, int widx0, const float* __restrict__ Bb0, const float* __restrict__ Bb1,
         const float* __restrict__ Bb2, const float* __restrict__ xres, int mode)
{
    extern __shared__ __align__(16) uint32_t sm[];
    const int bn=blockIdx.x, bm=blockIdx.y, z=blockIdx.z;
    const f16 *Ah = asel==0?g_xh: asel==1?g_mh:g_y1h;
    const f16 *Al = asel==0?g_xl: asel==1?g_ml:g_y1l;
    const f16 *Wh = g_w + (size_t)(widx0+z)*DD*DD;
    const float* Bb = z==0?Bb0 : z==1?Bb1 : Bb2;
    uint32_t sb = cvta_smem(sm);
    int tid=threadIdx.x, wid=tid>>5, lane=tid&31;
    int wm=wid&3, wn=wid>>2, tq=lane>>2, tr=lane&3;

    int aoff0 = a_ldsm_off(wm*32,      lane);
    int aoff1 = a_ldsm_off(wm*32+16,   lane);
    int boff0 = b_ldsm_off(wn*64,      lane);   // j stride 16 rows = 2304 B

    float acc[2][8][4];
    #pragma unroll
    for (int a=0;a<2;a++)
        #pragma unroll
        for (int b=0;b<8;b++)
            #pragma unroll
            for (int d=0;d<4;d++) acc[a][b][d]=0.0f;

    stage_cp(sb,             Ah, bm*128, 0, DD, 128);
    stage_cp(sb + TILEW*4,   Al, bm*128, 0, DD, 128);
    stage_cp(sb + TILEW*8,   Wh, bn*128, 0, DD, 128);
    CP_COMMIT;

    for (int c = 0; c < 12; c++){
        int buf = c & 1;
        if (c < 11){
            uint32_t nb = sb + ((c+1)&1)*(BUFW*4);
            stage_cp(nb,            Ah, bm*128, (c+1)*64, DD, 128);
            stage_cp(nb + TILEW*4,  Al, bm*128, (c+1)*64, DD, 128);
            stage_cp(nb + TILEW*8,  Wh, bn*128, (c+1)*64, DD, 128);
            CP_COMMIT;
            CP_WAIT1;
        } else {
            CP_WAIT0;
        }
        __syncthreads();
        uint32_t bA = sb + buf*(BUFW*4);
        uint32_t bAl = bA + TILEW*4, bB = bA + TILEW*8;
        #pragma unroll
        for (int kk = 0; kk < 4; kk++){
            int kbyte = kk*32;
            uint32_t a_h[2][4], a_l[2][4], b_h[8][2];
            ldsm4(a_h[0], bA  + aoff0 + kbyte);
            ldsm4(a_h[1], bA  + aoff1 + kbyte);
            ldsm4(a_l[0], bAl + aoff0 + kbyte);
            ldsm4(a_l[1], bAl + aoff1 + kbyte);
            #pragma unroll
            for (int j=0;j<4;j++)
                ldsm4(&b_h[2*j][0], bB + boff0 + j*2304 + kbyte);
            #pragma unroll
            for (int am=0;am<2;am++)
                #pragma unroll
                for (int an=0;an<8;an++){
                    mma16816(acc[am][an], a_h[am], b_h[an]);
                    mma16816(acc[am][an], a_l[am], b_h[an]);
                }
        }
        __syncthreads();
    }

    #pragma unroll
    for (int am=0;am<2;am++)
    #pragma unroll
    for (int rr=0;rr<2;rr++){
        int row = bm*128 + wm*32 + am*16 + tq + rr*8;
        #pragma unroll
        for (int an=0;an<8;an++){
            int col = bn*128 + wn*64 + an*8 + tr*2;
            float v0 = acc[am][an][rr*2]   + Bb[col];
            float v1 = acc[am][an][rr*2+1] + Bb[col+1];
            if (mode == 0){
                int b=row>>9, tok=row&511, h=col>>6, dk=col&63;
                if (z==0){
                    size_t off = ((size_t)(b*HH+h)*NN+tok)*DKK + dk;
                    f16 h0,l0,h1,l1; split2(v0,h0,l0); split2(v1,h1,l1);
                    *(uint32_t*)(g_qh+off) = pk(h0,h1);
                    *(uint32_t*)(g_ql+off) = pk(l0,l1);
                } else if (z==1){
                    size_t off = ((size_t)(b*HH+h)*NN+tok)*DKK + dk;
                    *(uint32_t*)(g_k+off) = pk(__float2half_rn(v0),__float2half_rn(v1));
                } else {
                    size_t base = ((size_t)(b*HH+h)*DKK + dk)*NN + tok;
                    g_vt[base]      = __float2half_rn(v0);
                    g_vt[base + NN] = __float2half_rn(v1);
                }
            } else if (mode == 1){
                v0 = v0/(1.0f+__expf(-v0)); v1 = v1/(1.0f+__expf(-v1));
                f16 h0,l0,h1,l1; split2(v0,h0,l0); split2(v1,h1,l1);
                size_t off = (size_t)row*DD + col;
                *(uint32_t*)(g_y1h+off) = pk(h0,h1);
                *(uint32_t*)(g_y1l+off) = pk(l0,l1);
            } else {
                size_t off = (size_t)row*DD + col;
                float2 xr = *(const float2*)(xres+off);
                float2 o; o.x = v0+xr.x; o.y = v1+xr.y;
                *(float2*)(g_preln+off) = o;
            }
        }
    }
}

// ---- scores: S[128x128] = Q @ K^T (K=64), mask*0.125 -> attn ----
#define SMEM_SC (BUFW*4)
__global__ void __launch_bounds__(256)
gemm_scores_tc(float* __restrict__ attn)
{
    extern __shared__ __align__(16) uint32_t sm[];
    const int bn=blockIdx.x, bm=blockIdx.y, z=blockIdx.z;
    const f16 *Qh=g_qh+(size_t)z*NN*DKK, *Ql=g_ql+(size_t)z*NN*DKK;
    const f16 *Kh=g_k +(size_t)z*NN*DKK;
    uint32_t sb = cvta_smem(sm);
    int tid=threadIdx.x, wid=tid>>5, lane=tid&31;
    int wm=wid&3, wn=wid>>2, tq=lane>>2, tr=lane&3;

    int aoff0 = a_ldsm_off(wm*32,    lane);
    int aoff1 = a_ldsm_off(wm*32+16, lane);
    int boff0 = b_ldsm_off(wn*64,    lane);

    float acc[2][8][4];
    #pragma unroll
    for (int a=0;a<2;a++)
        #pragma unroll
        for (int b=0;b<8;b++)
            #pragma unroll
            for (int d=0;d<4;d++) acc[a][b][d]=0.0f;

    stage_cp(sb,            Qh, bm*128, 0, DKK, 128);
    stage_cp(sb + TILEW*4,  Ql, bm*128, 0, DKK, 128);
    stage_cp(sb + TILEW*8,  Kh, bn*128, 0, DKK, 128);
    CP_COMMIT; CP_WAIT0;
    __syncthreads();

    uint32_t bAl = sb + TILEW*4, bB = sb + TILEW*8;
    #pragma unroll
    for (int kk = 0; kk < 4; kk++){
        int kbyte = kk*32;
        uint32_t a_h[2][4], a_l[2][4], b_h[8][2];
        ldsm4(a_h[0], sb  + aoff0 + kbyte);
        ldsm4(a_h[1], sb  + aoff1 + kbyte);
        ldsm4(a_l[0], bAl + aoff0 + kbyte);
        ldsm4(a_l[1], bAl + aoff1 + kbyte);
        #pragma unroll
        for (int j=0;j<4;j++)
            ldsm4(&b_h[2*j][0], bB + boff0 + j*2304 + kbyte);
        #pragma unroll
        for (int am=0;am<2;am++)
            #pragma unroll
            for (int an=0;an<8;an++){
                mma16816(acc[am][an], a_h[am], b_h[an]);
                mma16816(acc[am][an], a_l[am], b_h[an]);
            }
    }

    int b = z/HH;
    #pragma unroll
    for (int am=0;am<2;am++)
    #pragma unroll
    for (int rr=0;rr<2;rr++){
        int row = bm*128 + wm*32 + am*16 + tq + rr*8;
        const unsigned char* mr = g_mask + ((size_t)(b<<9)+row)*NN;
        #pragma unroll
        for (int an=0;an<8;an++){
            int col = bn*128 + wn*64 + an*8 + tr*2;
            float2 o;
            o.x = mr[col]   ? acc[am][an][rr*2]*0.125f   : -1e12f;
            o.y = mr[col+1] ? acc[am][an][rr*2+1]*0.125f : -1e12f;
            *(float2*)(attn + ((size_t)z*NN+row)*NN + col) = o;
        }
    }
}

// ---- softmax 512: normalize in place + emit fp16 hi/lo ----
__global__ void __launch_bounds__(128)
softmax512(float* __restrict__ attn)
{
    size_t rb = (size_t)blockIdx.x*NN;
    float* p = attn + rb;
    int tid = threadIdx.x;
    float v[4];
    #pragma unroll
    for (int i=0;i<4;i++) v[i]=p[tid+(i<<7)];
    float mx = fmaxf(fmaxf(v[0],v[1]),fmaxf(v[2],v[3]));
    #pragma unroll
    for (int o=16;o>0;o>>=1) mx=fmaxf(mx,__shfl_xor_sync(0xffffffffu,mx,o));
    __shared__ float smx[4], ssm[4];
    int wp=tid>>5, ln=tid&31;
    if (ln==0) smx[wp]=mx;
    __syncthreads();
    mx = fmaxf(fmaxf(smx[0],smx[1]),fmaxf(smx[2],smx[3]));
    float s=0.0f;
    #pragma unroll
    for (int i=0;i<4;i++){ v[i]=__expf(v[i]-mx); s+=v[i]; }
    #pragma unroll
    for (int o=16;o>0;o>>=1) s+=__shfl_xor_sync(0xffffffffu,s,o);
    if (ln==0) ssm[wp]=s;
    __syncthreads();
    s = ssm[0]+ssm[1]+ssm[2]+ssm[3];
    float inv = 1.0f/s;
    #pragma unroll
    for (int i=0;i<4;i++){
        float val = v[i]*inv;
        int idx = tid+(i<<7);
        p[idx] = val;
        f16 hh, hl; split2(val, hh, hl);
        g_ph[rb+idx] = hh;
        g_pl[rb+idx] = hl;
    }
}

// ---- msg = attn @ V : 128x64 tile, K=512, ldmatrix + cp.async dbuf ----
#define BTILEW 2304
#define MBUFW (2*TILEW + BTILEW)
#define SMEM_MSG (2*MBUFW*4)
__global__ void __launch_bounds__(256)
gemm_msg_tc(void)
{
    extern __shared__ __align__(16) uint32_t sm[];
    const int bm=blockIdx.x, z=blockIdx.y;
    const f16 *Ahp = g_ph + (size_t)z*NN*NN;
    const f16 *Alp = g_pl + (size_t)z*NN*NN;
    const f16 *Vt  = g_vt + (size_t)z*DKK*NN;
    uint32_t sb = cvta_smem(sm);
    int tid=threadIdx.x, wid=tid>>5, lane=tid&31;
    int wm=wid&3, wn=wid>>2, tq=lane>>2, tr=lane&3;

    int aoff0 = a_ldsm_off(wm*32,    lane);
    int aoff1 = a_ldsm_off(wm*32+16, lane);
    int boff0 = b_ldsm_off(wn*32,    lane);   // j stride 2304 B (j=0,1)

    float acc[2][4][4];
    #pragma unroll
    for (int a=0;a<2;a++)
        #pragma unroll
        for (int b=0;b<4;b++)
            #pragma unroll
            for (int d=0;d<4;d++) acc[a][b][d]=0.0f;

    stage_cp(sb,            Ahp, bm*128, 0, NN, 128);
    stage_cp(sb + TILEW*4,  Alp, bm*128, 0, NN, 128);
    stage_cp(sb + TILEW*8,  Vt,  0,      0, NN, 64);
    CP_COMMIT;

    for (int c = 0; c < 8; c++){
        int buf = c & 1;
        if (c < 7){
            uint32_t nb = sb + ((c+1)&1)*(MBUFW*4);
            stage_cp(nb,            Ahp, bm*128, (c+1)*64, NN, 128);
            stage_cp(nb + TILEW*4,  Alp, bm*128, (c+1)*64, NN, 128);
            stage_cp(nb + TILEW*8,  Vt,  0,      (c+1)*64, NN, 64);
            CP_COMMIT;
            CP_WAIT1;
        } else {
            CP_WAIT0;
        }
        __syncthreads();
        uint32_t bA = sb + buf*(MBUFW*4);
        uint32_t bAl = bA + TILEW*4, bB = bA + TILEW*8;
        #pragma unroll
        for (int kk = 0; kk < 4; kk++){
            int kbyte = kk*32;
            uint32_t a_h[2][4], a_l[2][4], b_h[4][2];
            ldsm4(a_h[0], bA  + aoff0 + kbyte);
            ldsm4(a_h[1], bA  + aoff1 + kbyte);
            ldsm4(a_l[0], bAl + aoff0 + kbyte);
            ldsm4(a_l[1], bAl + aoff1 + kbyte);
            #pragma unroll
            for (int j=0;j<2;j++)
                ldsm4(&b_h[2*j][0], bB + boff0 + j*2304 + kbyte);
            #pragma unroll
            for (int am=0;am<2;am++)
                #pragma unroll
                for (int an=0;an<4;an++){
                    mma16816(acc[am][an], a_h[am], b_h[an]);
                    mma16816(acc[am][an], a_l[am], b_h[an]);
                }
        }
        __syncthreads();
    }

    int b = z/HH, h = z%HH;
    #pragma unroll
    for (int am=0;am<2;am++)
    #pragma unroll
    for (int rr=0;rr<2;rr++){
        int tok = bm*128 + wm*32 + am*16 + tq + rr*8;
        #pragma unroll
        for (int an=0;an<4;an++){
            int dk = wn*32 + an*8 + tr*2;
            f16 h0,l0,h1,l1;
            split2(acc[am][an][rr*2],h0,l0); split2(acc[am][an][rr*2+1],h1,l1);
            size_t off = ((size_t)(b*NN+tok))*DD + h*DKK + dk;
            *(uint32_t*)(g_mh+off) = pk(h0,h1);
            *(uint32_t*)(g_ml+off) = pk(l0,l1);
        }
    }
}

// ---- layernorm (proven) ----
__global__ void __launch_bounds__(256)
layernorm(const float* __restrict__ gam, const float* __restrict__ bet, float* __restrict__ out)
{
    int row = blockIdx.x, tid = threadIdx.x;
    const float* p = g_preln + (size_t)row*DD;
    float x0=p[tid], x1=p[tid+256], x2=p[tid+512];
    __shared__ float red[256];
    red[tid]=x0+x1+x2; __syncthreads();
    for (int o=128;o>0;o>>=1){ if (tid<o) red[tid]+=red[tid+o]; __syncthreads(); }
    float mu = red[0]*(1.0f/768.0f); __syncthreads();
    float d0=x0-mu, d1=x1-mu, d2=x2-mu;
    red[tid]=d0*d0+d1*d1+d2*d2; __syncthreads();
    for (int o=128;o>0;o>>=1){ if (tid<o) red[tid]+=red[tid+o]; __syncthreads(); }
    float inv = 1.0f/sqrtf(red[0]*(1.0f/768.0f)+1e-6f);
    float* o = out + (size_t)row*DD;
    o[tid]     = d0*inv*gam[tid]     + bet[tid];
    o[tid+256] = d1*inv*gam[tid+256] + bet[tid+256];
    o[tid+512] = d2*inv*gam[tid+512] + bet[tid+512];
}

extern "C" void kernel_launch(void* const* d_in, const int* in_sizes, int n_in,
                              void* d_out, int out_size)
{
    const float* x    = (const float*)d_in[0];
    const float* dist = (const float*)d_in[1];
    const float* q_w  = (const float*)d_in[2];
    const float* q_b  = (const float*)d_in[3];
    const float* k_w  = (const float*)d_in[4];
    const float* k_b  = (const float*)d_in[5];
    const float* v_w  = (const float*)d_in[6];
    const float* v_b  = (const float*)d_in[7];
    const float* s1_w = (const float*)d_in[8];
    const float* s1_b = (const float*)d_in[9];
    const float* s2_w = (const float*)d_in[10];
    const float* s2_b = (const float*)d_in[11];
    const float* ln_g = (const float*)d_in[12];
    const float* ln_b = (const float*)d_in[13];

    float* out  = (float*)d_out;
    float* attn = out + (size_t)MROWS*DD;

    cudaFuncSetAttribute(gemm_big,       cudaFuncAttributeMaxDynamicSharedMemorySize, SMEM_BIG);
    cudaFuncSetAttribute(gemm_scores_tc, cudaFuncAttributeMaxDynamicSharedMemorySize, SMEM_SC);
    cudaFuncSetAttribute(gemm_msg_tc,    cudaFuncAttributeMaxDynamicSharedMemorySize, SMEM_MSG);

    const size_t WSZ = (size_t)DD*DD;
    conv_split_x<<<(MROWS*DD/4+255)/256, 256>>>(x, MROWS*DD/4);
    conv_h<<<(int)(WSZ/4+255)/256, 256>>>(q_w,  0*WSZ, (int)(WSZ/4));
    conv_h<<<(int)(WSZ/4+255)/256, 256>>>(k_w,  1*WSZ, (int)(WSZ/4));
    conv_h<<<(int)(WSZ/4+255)/256, 256>>>(v_w,  2*WSZ, (int)(WSZ/4));
    conv_h<<<(int)(WSZ/4+255)/256, 256>>>(s1_w, 3*WSZ, (int)(WSZ/4));
    conv_h<<<(int)(WSZ/4+255)/256, 256>>>(s2_w, 4*WSZ, (int)(WSZ/4));

    build_mask<<<BB*NN, 256>>>(dist);

    gemm_big<<<dim3(DD/128, MROWS/128, 3), 256, SMEM_BIG>>>(0, 0, q_b, k_b, v_b, x, 0);
    gemm_scores_tc<<<dim3(NN/128, NN/128, BHZ), 256, SMEM_SC>>>(attn);
    softmax512<<<BHZ*NN, 128>>>(attn);
    gemm_msg_tc<<<dim3(NN/128, BHZ), 256, SMEM_MSG>>>();
    gemm_big<<<dim3(DD/128, MROWS/128, 1), 256, SMEM_BIG>>>(1, 3, s1_b, s1_b, s1_b, x, 1);
    gemm_big<<<dim3(DD/128, MROWS/128, 1), 256, SMEM_BIG>>>(2, 4, s2_b, s2_b, s2_b, x, 2);
    layernorm<<<MROWS, 256>>>(ln_g, ln_b, out);
}

// round 13
// speedup vs baseline: 3.2994x; 1.1101x over previous
#include <cuda_runtime.h>
#include <cuda_fp16.h>
#include <math.h>
#include <stdint.h>

#define BB 16
#define NN 512
#define HH 12
#define DKK 64
#define DD 768
#define BHZ 192
#define MROWS 8192
#define KNN 153

typedef __half f16;

__device__ __align__(128) f16 g_xh[(size_t)MROWS*DD], g_xl[(size_t)MROWS*DD];
__device__ __align__(128) f16 g_w [(size_t)5*DD*DD];
__device__ __align__(128) f16 g_qh[(size_t)BHZ*NN*DKK], g_ql[(size_t)BHZ*NN*DKK];
__device__ __align__(128) f16 g_k [(size_t)BHZ*NN*DKK];
__device__ __align__(128) f16 g_vt[(size_t)BHZ*DKK*NN];
__device__ __align__(128) f16 g_mh[(size_t)MROWS*DD],  g_ml[(size_t)MROWS*DD];
__device__ __align__(128) f16 g_y1h[(size_t)MROWS*DD], g_y1l[(size_t)MROWS*DD];
__device__ float g_preln[(size_t)MROWS*DD];
__device__ unsigned char g_mask[(size_t)BB*NN*NN];

__device__ __forceinline__ void split2(float v, f16& h, f16& l){
    h = __float2half_rn(v); l = __float2half_rn(v - __half2float(h));
}
__device__ __forceinline__ uint32_t pk(f16 a, f16 b){
    uint16_t x = *(uint16_t*)&a, y = *(uint16_t*)&b;
    return (uint32_t)x | ((uint32_t)y << 16);
}
__device__ __forceinline__ uint32_t pk2(float a, float b){
    f16 x = __float2half_rn(a), y = __float2half_rn(b);
    return pk(x,y);
}
__device__ __forceinline__ void mma16816(float* c, const uint32_t* a, const uint32_t* b){
    asm volatile("mma.sync.aligned.m16n8k16.row.col.f32.f16.f16.f32 "
        "{%0,%1,%2,%3}, {%4,%5,%6,%7}, {%8,%9}, {%0,%1,%2,%3};"
        : "+f"(c[0]),"+f"(c[1]),"+f"(c[2]),"+f"(c[3])
        : "r"(a[0]),"r"(a[1]),"r"(a[2]),"r"(a[3]),"r"(b[0]),"r"(b[1]));
}
__device__ __forceinline__ void ldsm4(uint32_t* r, uint32_t addr){
    asm volatile("ldmatrix.sync.aligned.m8n8.x4.shared.b16 {%0,%1,%2,%3}, [%4];"
        : "=r"(r[0]),"=r"(r[1]),"=r"(r[2]),"=r"(r[3]) : "r"(addr));
}
__device__ __forceinline__ uint32_t cvta_smem(const void* p){
    uint32_t a; asm("{ .reg .u64 t; cvta.to.shared.u64 t, %1; cvt.u32.u64 %0, t; }":"=r"(a):"l"(p)); return a;
}
__device__ __forceinline__ void cpa16(uint32_t dst, const void* src){
    asm volatile("cp.async.cg.shared.global [%0], [%1], 16;"::"r"(dst),"l"(src));
}
#define CP_COMMIT asm volatile("cp.async.commit_group;")
#define CP_WAIT0  asm volatile("cp.async.wait_group 0;")
#define CP_WAIT1  asm volatile("cp.async.wait_group 1;")

__device__ __forceinline__ void stage_cp(uint32_t dst, const f16* src, int row0, int k0, int ld, int nrows){
    for (int i = threadIdx.x; i < nrows*8; i += 256){
        int r = i>>3, s = i&7;
        cpa16(dst + r*144 + s*16, src + (size_t)(row0+r)*ld + k0 + s*8);
    }
}
__device__ __forceinline__ int a_ldsm_off(int mrow0, int lane){
    return ((mrow0 + (lane&7) + ((lane>>3)&1)*8)*36 + (lane>>4)*4)*4;
}
__device__ __forceinline__ int b_ldsm_off(int nrow0, int lane){
    return ((nrow0 + (lane&7) + ((lane>>4)&1)*8)*36 + ((lane>>3)&1)*4)*4;
}

// ---- fp32 -> fp16 hi/lo (x) ----
__global__ void __launch_bounds__(256)
conv_split_x(const float* __restrict__ src, int n4)
{
    int i = blockIdx.x*256 + threadIdx.x;
    if (i >= n4) return;
    float4 v = ((const float4*)src)[i];
    f16 h[4], l[4];
    split2(v.x,h[0],l[0]); split2(v.y,h[1],l[1]); split2(v.z,h[2],l[2]); split2(v.w,h[3],l[3]);
    ((uint2*)g_xh)[i] = *(uint2*)h; ((uint2*)g_xl)[i] = *(uint2*)l;
}
__global__ void __launch_bounds__(256)
conv_h(const float* __restrict__ src, size_t off, int n4)
{
    int i = blockIdx.x*256 + threadIdx.x;
    if (i >= n4) return;
    float4 v = ((const float4*)src)[i];
    f16 h[4];
    h[0]=__float2half_rn(v.x); h[1]=__float2half_rn(v.y);
    h[2]=__float2half_rn(v.z); h[3]=__float2half_rn(v.w);
    ((uint2*)(g_w+off))[i] = *(uint2*)h;
}

// ---- kNN mask (proven) ----
__global__ void __launch_bounds__(256)
build_mask(const float* __restrict__ dist)
{
    int b = blockIdx.x>>9, n = blockIdx.x&511, tid = threadIdx.x;
    unsigned char* mrow = g_mask + ((size_t)(b<<9)+n)*NN;
    if (n == 0){ for (int m=tid;m<NN;m+=256) mrow[m]=1; return; }
    __shared__ unsigned long long key[512];
    for (int m=tid;m<NN;m+=256){
        float v = (m==0)?0.0f:dist[(size_t)(b*511+(n-1))*511+(m-1)];
        key[m] = ((unsigned long long)__float_as_uint(v)<<32) | (unsigned)m;
    }
    __syncthreads();
    for (int k=2;k<=512;k<<=1) for (int j=k>>1;j>0;j>>=1){
        for (int i=tid;i<512;i+=256){
            int x = i^j;
            if (x>i){ bool up=((i&k)==0); unsigned long long a=key[i],c=key[x];
                if ((a>c)==up){ key[i]=c; key[x]=a; } }
        }
        __syncthreads();
    }
    for (int m=tid;m<NN;m+=256) mrow[m]=0;
    __syncthreads();
    for (int s=tid;s<KNN;s+=256) mrow[(int)(key[s]&511u)]=1;
    if (tid==0) mrow[0]=1;
}

// ---- big GEMM (proven R11) ----
#define TILEW 4608
#define BUFW  (3*TILEW)
#define SMEM_BIG (2*BUFW*4)
__global__ void __launch_bounds__(256)
gemm_big(int asel, int widx0, const float* __restrict__ Bb0, const float* __restrict__ Bb1,
         const float* __restrict__ Bb2, const float* __restrict__ xres, int mode)
{
    extern __shared__ __align__(16) uint32_t sm[];
    const int bn=blockIdx.x, bm=blockIdx.y, z=blockIdx.z;
    const f16 *Ah = asel==0?g_xh: asel==1?g_mh:g_y1h;
    const f16 *Al = asel==0?g_xl: asel==1?g_ml:g_y1l;
    const f16 *Wh = g_w + (size_t)(widx0+z)*DD*DD;
    const float* Bb = z==0?Bb0 : z==1?Bb1 : Bb2;
    uint32_t sb = cvta_smem(sm);
    int tid=threadIdx.x, wid=tid>>5, lane=tid&31;
    int wm=wid&3, wn=wid>>2, tq=lane>>2, tr=lane&3;

    int aoff0 = a_ldsm_off(wm*32,      lane);
    int aoff1 = a_ldsm_off(wm*32+16,   lane);
    int boff0 = b_ldsm_off(wn*64,      lane);

    float acc[2][8][4];
    #pragma unroll
    for (int a=0;a<2;a++)
        #pragma unroll
        for (int b=0;b<8;b++)
            #pragma unroll
            for (int d=0;d<4;d++) acc[a][b][d]=0.0f;

    stage_cp(sb,             Ah, bm*128, 0, DD, 128);
    stage_cp(sb + TILEW*4,   Al, bm*128, 0, DD, 128);
    stage_cp(sb + TILEW*8,   Wh, bn*128, 0, DD, 128);
    CP_COMMIT;

    for (int c = 0; c < 12; c++){
        int buf = c & 1;
        if (c < 11){
            uint32_t nb = sb + ((c+1)&1)*(BUFW*4);
            stage_cp(nb,            Ah, bm*128, (c+1)*64, DD, 128);
            stage_cp(nb + TILEW*4,  Al, bm*128, (c+1)*64, DD, 128);
            stage_cp(nb + TILEW*8,  Wh, bn*128, (c+1)*64, DD, 128);
            CP_COMMIT;
            CP_WAIT1;
        } else {
            CP_WAIT0;
        }
        __syncthreads();
        uint32_t bA = sb + buf*(BUFW*4);
        uint32_t bAl = bA + TILEW*4, bB = bA + TILEW*8;
        #pragma unroll
        for (int kk = 0; kk < 4; kk++){
            int kbyte = kk*32;
            uint32_t a_h[2][4], a_l[2][4], b_h[8][2];
            ldsm4(a_h[0], bA  + aoff0 + kbyte);
            ldsm4(a_h[1], bA  + aoff1 + kbyte);
            ldsm4(a_l[0], bAl + aoff0 + kbyte);
            ldsm4(a_l[1], bAl + aoff1 + kbyte);
            #pragma unroll
            for (int j=0;j<4;j++)
                ldsm4(&b_h[2*j][0], bB + boff0 + j*2304 + kbyte);
            #pragma unroll
            for (int am=0;am<2;am++)
                #pragma unroll
                for (int an=0;an<8;an++){
                    mma16816(acc[am][an], a_h[am], b_h[an]);
                    mma16816(acc[am][an], a_l[am], b_h[an]);
                }
        }
        __syncthreads();
    }

    #pragma unroll
    for (int am=0;am<2;am++)
    #pragma unroll
    for (int rr=0;rr<2;rr++){
        int row = bm*128 + wm*32 + am*16 + tq + rr*8;
        #pragma unroll
        for (int an=0;an<8;an++){
            int col = bn*128 + wn*64 + an*8 + tr*2;
            float v0 = acc[am][an][rr*2]   + Bb[col];
            float v1 = acc[am][an][rr*2+1] + Bb[col+1];
            if (mode == 0){
                int b=row>>9, tok=row&511, h=col>>6, dk=col&63;
                if (z==0){
                    size_t off = ((size_t)(b*HH+h)*NN+tok)*DKK + dk;
                    f16 h0,l0,h1,l1; split2(v0,h0,l0); split2(v1,h1,l1);
                    *(uint32_t*)(g_qh+off) = pk(h0,h1);
                    *(uint32_t*)(g_ql+off) = pk(l0,l1);
                } else if (z==1){
                    size_t off = ((size_t)(b*HH+h)*NN+tok)*DKK + dk;
                    *(uint32_t*)(g_k+off) = pk2(v0,v1);
                } else {
                    size_t base = ((size_t)(b*HH+h)*DKK + dk)*NN + tok;
                    g_vt[base]      = __float2half_rn(v0);
                    g_vt[base + NN] = __float2half_rn(v1);
                }
            } else if (mode == 1){
                v0 = v0/(1.0f+__expf(-v0)); v1 = v1/(1.0f+__expf(-v1));
                f16 h0,l0,h1,l1; split2(v0,h0,l0); split2(v1,h1,l1);
                size_t off = (size_t)row*DD + col;
                *(uint32_t*)(g_y1h+off) = pk(h0,h1);
                *(uint32_t*)(g_y1l+off) = pk(l0,l1);
            } else {
                size_t off = (size_t)row*DD + col;
                float2 xr = *(const float2*)(xres+off);
                float2 o; o.x = v0+xr.x; o.y = v1+xr.y;
                *(float2*)(g_preln+off) = o;
            }
        }
    }
}

// ---- fused attention: scores + mask + softmax + attn write + P·V ----
#define QH0 0
#define QL0 2304
#define K0  4608
#define V0  23040
#define MSG0 39680
#define REDM 44032
#define REDS 44288
#define SMEM_ATT (44544*4)
__global__ void __launch_bounds__(256, 1)
attn_fused(float* __restrict__ attn)
{
    extern __shared__ __align__(16) uint32_t sm[];
    const int bm = blockIdx.x, z = blockIdx.y;
    const int bb = z/HH, hh = z%HH;
    uint32_t sb = cvta_smem(sm);
    int tid=threadIdx.x, wid=tid>>5, lane=tid&31;
    int wm=wid&1, wn=wid>>1, tq=lane>>2, tr=lane&3;

    // stage Q (64 rows), K (512 rows), V^T (64 rows x 512 tok, stride 1040B)
    stage_cp(sb + QH0*4, g_qh + (size_t)z*NN*DKK, bm*64, 0, DKK, 64);
    stage_cp(sb + QL0*4, g_ql + (size_t)z*NN*DKK, bm*64, 0, DKK, 64);
    stage_cp(sb + K0*4,  g_k  + (size_t)z*NN*DKK, 0,     0, DKK, 512);
    {
        const f16* Vt = g_vt + (size_t)z*DKK*NN;
        for (int i = tid; i < 4096; i += 256){              // FIXED: full 64x512 tile
            int r = i>>6, s = i&63;
            cpa16(sb + V0*4 + r*1040 + s*16, Vt + (size_t)r*NN + s*8);
        }
    }
    CP_COMMIT; CP_WAIT0;
    __syncthreads();

    // ---- scores ----
    float acc[2][16][4];
    #pragma unroll
    for (int a=0;a<2;a++)
        #pragma unroll
        for (int b=0;b<16;b++)
            #pragma unroll
            for (int d=0;d<4;d++) acc[a][b][d]=0.0f;

    int aoff0 = a_ldsm_off(wm*32,    lane);
    int aoff1 = a_ldsm_off(wm*32+16, lane);
    int boff  = b_ldsm_off(wn*128,   lane);
    #pragma unroll
    for (int kk = 0; kk < 4; kk++){
        int kbyte = kk*32;
        uint32_t a_h[2][4], a_l[2][4], b_h[16][2];
        ldsm4(a_h[0], sb + QH0*4 + aoff0 + kbyte);
        ldsm4(a_h[1], sb + QH0*4 + aoff1 + kbyte);
        ldsm4(a_l[0], sb + QL0*4 + aoff0 + kbyte);
        ldsm4(a_l[1], sb + QL0*4 + aoff1 + kbyte);
        #pragma unroll
        for (int j=0;j<8;j++)
            ldsm4(&b_h[2*j][0], sb + K0*4 + boff + j*2304 + kbyte);
        #pragma unroll
        for (int am=0;am<2;am++)
            #pragma unroll
            for (int an=0;an<16;an++){
                mma16816(acc[am][an], a_h[am], b_h[an]);
                mma16816(acc[am][an], a_l[am], b_h[an]);
            }
    }

    // ---- mask + scale ----
    #pragma unroll
    for (int am=0;am<2;am++)
    #pragma unroll
    for (int rr=0;rr<2;rr++){
        int row = bm*64 + wm*32 + am*16 + tq + rr*8;
        const unsigned char* mr = g_mask + ((size_t)(bb<<9)+row)*NN;
        #pragma unroll
        for (int an=0;an<16;an++){
            int col = wn*128 + an*8 + tr*2;
            acc[am][an][rr*2]   = mr[col]   ? acc[am][an][rr*2]*0.125f   : -1e12f;
            acc[am][an][rr*2+1] = mr[col+1] ? acc[am][an][rr*2+1]*0.125f : -1e12f;
        }
    }

    float* sRedM = (float*)(sm + REDM);
    float* sRedS = (float*)(sm + REDS);

    // ---- row max ----
    float mx[2][2];
    #pragma unroll
    for (int am=0;am<2;am++)
    #pragma unroll
    for (int rr=0;rr<2;rr++){
        float m = -1e30f;
        #pragma unroll
        for (int an=0;an<16;an++)
            m = fmaxf(m, fmaxf(acc[am][an][rr*2], acc[am][an][rr*2+1]));
        m = fmaxf(m, __shfl_xor_sync(0xffffffffu, m, 1));
        m = fmaxf(m, __shfl_xor_sync(0xffffffffu, m, 2));
        if (tr==0) sRedM[(wm*32+am*16+tq+rr*8)*4 + wn] = m;
        mx[am][rr] = m;
    }
    __syncthreads();
    #pragma unroll
    for (int am=0;am<2;am++)
    #pragma unroll
    for (int rr=0;rr<2;rr++){
        const float* p = sRedM + (wm*32+am*16+tq+rr*8)*4;
        mx[am][rr] = fmaxf(fmaxf(p[0],p[1]), fmaxf(p[2],p[3]));
    }

    // ---- exp + row sum ----
    float sumv[2][2];
    #pragma unroll
    for (int am=0;am<2;am++)
    #pragma unroll
    for (int rr=0;rr<2;rr++){
        float s = 0.0f;
        #pragma unroll
        for (int an=0;an<16;an++){
            float p0 = __expf(acc[am][an][rr*2]   - mx[am][rr]);
            float p1 = __expf(acc[am][an][rr*2+1] - mx[am][rr]);
            acc[am][an][rr*2] = p0; acc[am][an][rr*2+1] = p1;
            s += p0 + p1;
        }
        s += __shfl_xor_sync(0xffffffffu, s, 1);
        s += __shfl_xor_sync(0xffffffffu, s, 2);
        if (tr==0) sRedS[(wm*32+am*16+tq+rr*8)*4 + wn] = s;
        sumv[am][rr] = s;
    }
    __syncthreads();
    #pragma unroll
    for (int am=0;am<2;am++)
    #pragma unroll
    for (int rr=0;rr<2;rr++){
        const float* p = sRedS + (wm*32+am*16+tq+rr*8)*4;
        sumv[am][rr] = 1.0f/(p[0]+p[1]+p[2]+p[3]);
    }

    // ---- normalize + write attn fp32 ----
    #pragma unroll
    for (int am=0;am<2;am++)
    #pragma unroll
    for (int rr=0;rr<2;rr++){
        int row = bm*64 + wm*32 + am*16 + tq + rr*8;
        float inv = sumv[am][rr];
        #pragma unroll
        for (int an=0;an<16;an++){
            float v0 = acc[am][an][rr*2]*inv, v1 = acc[am][an][rr*2+1]*inv;
            acc[am][an][rr*2] = v0; acc[am][an][rr*2+1] = v1;
            float2 o; o.x=v0; o.y=v1;
            *(float2*)(attn + ((size_t)z*NN+row)*NN + wn*128 + an*8 + tr*2) = o;
        }
    }

    // ---- P·V : repack C-frags -> A-frags (hi/lo), mma against V^T ----
    float macc[2][8][4];
    #pragma unroll
    for (int a=0;a<2;a++)
        #pragma unroll
        for (int b=0;b<8;b++)
            #pragma unroll
            for (int d=0;d<4;d++) macc[a][b][d]=0.0f;

    int vlane = ((lane&7) + ((lane>>4)&1)*8)*1040 + ((lane>>3)&1)*16;
    int kwarp = wn*256;
    #pragma unroll
    for (int kj = 0; kj < 8; kj++){
        uint32_t aPh[2][4], aPl[2][4];
        #pragma unroll
        for (int am=0;am<2;am++){
            f16 h0,l0,h1,l1;
            split2(acc[am][2*kj][0],h0,l0);  split2(acc[am][2*kj][1],h1,l1);
            aPh[am][0]=pk(h0,h1); aPl[am][0]=pk(l0,l1);
            split2(acc[am][2*kj][2],h0,l0);  split2(acc[am][2*kj][3],h1,l1);
            aPh[am][1]=pk(h0,h1); aPl[am][1]=pk(l0,l1);
            split2(acc[am][2*kj+1][0],h0,l0); split2(acc[am][2*kj+1][1],h1,l1);
            aPh[am][2]=pk(h0,h1); aPl[am][2]=pk(l0,l1);
            split2(acc[am][2*kj+1][2],h0,l0); split2(acc[am][2*kj+1][3],h1,l1);
            aPh[am][3]=pk(h0,h1); aPl[am][3]=pk(l0,l1);
        }
        uint32_t bV[8][2];
        #pragma unroll
        for (int j=0;j<4;j++)
            ldsm4(&bV[2*j][0], sb + V0*4 + vlane + j*16*1040 + kwarp + kj*32);
        #pragma unroll
        for (int am=0;am<2;am++)
            #pragma unroll
            for (int an=0;an<8;an++){
                mma16816(macc[am][an], aPh[am], bV[an]);
                mma16816(macc[am][an], aPl[am], bV[an]);
            }
    }

    // ---- cross-warp (wn) k-slice reduction in smem ----
    float* sMsg = (float*)(sm + MSG0);
    #pragma unroll
    for (int w=0; w<4; w++){
        if (wn == w){
            #pragma unroll
            for (int am=0;am<2;am++)
            #pragma unroll
            for (int rr=0;rr<2;rr++){
                int r = wm*32 + am*16 + tq + rr*8;
                #pragma unroll
                for (int an=0;an<8;an++){
                    float* p = sMsg + r*68 + an*8 + tr*2;
                    if (w==0){ p[0] = macc[am][an][rr*2]; p[1] = macc[am][an][rr*2+1]; }
                    else     { p[0]+= macc[am][an][rr*2]; p[1]+= macc[am][an][rr*2+1]; }
                }
            }
        }
        __syncthreads();
    }

    // ---- write msg (fp16 hi/lo) ----
    {
        int r = tid>>2, cq = (tid&3)*16;
        int tok = bm*64 + r;
        size_t base = ((size_t)(bb*NN+tok))*DD + hh*DKK + cq;
        #pragma unroll
        for (int i=0;i<8;i++){
            float v0 = sMsg[r*68 + cq + 2*i], v1 = sMsg[r*68 + cq + 2*i + 1];
            f16 h0,l0,h1,l1; split2(v0,h0,l0); split2(v1,h1,l1);
            *(uint32_t*)(g_mh + base + 2*i) = pk(h0,h1);
            *(uint32_t*)(g_ml + base + 2*i) = pk(l0,l1);
        }
    }
}

// ---- layernorm (proven) ----
__global__ void __launch_bounds__(256)
layernorm(const float* __restrict__ gam, const float* __restrict__ bet, float* __restrict__ out)
{
    int row = blockIdx.x, tid = threadIdx.x;
    const float* p = g_preln + (size_t)row*DD;
    float x0=p[tid], x1=p[tid+256], x2=p[tid+512];
    __shared__ float red[256];
    red[tid]=x0+x1+x2; __syncthreads();
    for (int o=128;o>0;o>>=1){ if (tid<o) red[tid]+=red[tid+o]; __syncthreads(); }
    float mu = red[0]*(1.0f/768.0f); __syncthreads();
    float d0=x0-mu, d1=x1-mu, d2=x2-mu;
    red[tid]=d0*d0+d1*d1+d2*d2; __syncthreads();
    for (int o=128;o>0;o>>=1){ if (tid<o) red[tid]+=red[tid+o]; __syncthreads(); }
    float inv = 1.0f/sqrtf(red[0]*(1.0f/768.0f)+1e-6f);
    float* o = out + (size_t)row*DD;
    o[tid]     = d0*inv*gam[tid]     + bet[tid];
    o[tid+256] = d1*inv*gam[tid+256] + bet[tid+256];
    o[tid+512] = d2*inv*gam[tid+512] + bet[tid+512];
}

extern "C" void kernel_launch(void* const* d_in, const int* in_sizes, int n_in,
                              void* d_out, int out_size)
{
    const float* x    = (const float*)d_in[0];
    const float* dist = (const float*)d_in[1];
    const float* q_w  = (const float*)d_in[2];
    const float* q_b  = (const float*)d_in[3];
    const float* k_w  = (const float*)d_in[4];
    const float* k_b  = (const float*)d_in[5];
    const float* v_w  = (const float*)d_in[6];
    const float* v_b  = (const float*)d_in[7];
    const float* s1_w = (const float*)d_in[8];
    const float* s1_b = (const float*)d_in[9];
    const float* s2_w = (const float*)d_in[10];
    const float* s2_b = (const float*)d_in[11];
    const float* ln_g = (const float*)d_in[12];
    const float* ln_b = (const float*)d_in[13];

    float* out  = (float*)d_out;
    float* attn = out + (size_t)MROWS*DD;

    cudaFuncSetAttribute(gemm_big,   cudaFuncAttributeMaxDynamicSharedMemorySize, SMEM_BIG);
    cudaFuncSetAttribute(attn_fused, cudaFuncAttributeMaxDynamicSharedMemorySize, SMEM_ATT);

    const size_t WSZ = (size_t)DD*DD;
    conv_split_x<<<(MROWS*DD/4+255)/256, 256>>>(x, MROWS*DD/4);
    conv_h<<<(int)(WSZ/4+255)/256, 256>>>(q_w,  0*WSZ, (int)(WSZ/4));
    conv_h<<<(int)(WSZ/4+255)/256, 256>>>(k_w,  1*WSZ, (int)(WSZ/4));
    conv_h<<<(int)(WSZ/4+255)/256, 256>>>(v_w,  2*WSZ, (int)(WSZ/4));
    conv_h<<<(int)(WSZ/4+255)/256, 256>>>(s1_w, 3*WSZ, (int)(WSZ/4));
    conv_h<<<(int)(WSZ/4+255)/256, 256>>>(s2_w, 4*WSZ, (int)(WSZ/4));

    build_mask<<<BB*NN, 256>>>(dist);

    gemm_big<<<dim3(DD/128, MROWS/128, 3), 256, SMEM_BIG>>>(0, 0, q_b, k_b, v_b, x, 0);
    attn_fused<<<dim3(NN/64, BHZ), 256, SMEM_ATT>>>(attn);
    gemm_big<<<dim3(DD/128, MROWS/128, 1), 256, SMEM_BIG>>>(1, 3, s1_b, s1_b, s1_b, x, 1);
    gemm_big<<<dim3(DD/128, MROWS/128, 1), 256, SMEM_BIG>>>(2, 4, s2_b, s2_b, s2_b, x, 2);
    layernorm<<<MROWS, 256>>>(ln_g, ln_b, out);
}

// round 14
// speedup vs baseline: 4.0919x; 1.2402x over previous
#include <cuda_runtime.h>
#include <cuda_fp16.h>
#include <math.h>
#include <stdint.h>

#define BB 16
#define NN 512
#define HH 12
#define DKK 64
#define DD 768
#define BHZ 192
#define MROWS 8192
#define KNN 153

typedef __half f16;

__device__ __align__(128) f16 g_xh[(size_t)MROWS*DD];
__device__ __align__(128) f16 g_w [(size_t)5*DD*DD];
__device__ __align__(128) f16 g_qh[(size_t)BHZ*NN*DKK], g_ql[(size_t)BHZ*NN*DKK];
__device__ __align__(128) f16 g_k [(size_t)BHZ*NN*DKK];
__device__ __align__(128) f16 g_vt[(size_t)BHZ*DKK*NN];
__device__ __align__(128) f16 g_mh[(size_t)MROWS*DD];
__device__ __align__(128) f16 g_y1h[(size_t)MROWS*DD];
__device__ float g_preln[(size_t)MROWS*DD];
__device__ unsigned char g_mask[(size_t)BB*NN*NN];

__device__ __forceinline__ void split2(float v, f16& h, f16& l){
    h = __float2half_rn(v); l = __float2half_rn(v - __half2float(h));
}
__device__ __forceinline__ uint32_t pk(f16 a, f16 b){
    uint16_t x = *(uint16_t*)&a, y = *(uint16_t*)&b;
    return (uint32_t)x | ((uint32_t)y << 16);
}
__device__ __forceinline__ uint32_t pk2(float a, float b){
    f16 x = __float2half_rn(a), y = __float2half_rn(b);
    return pk(x,y);
}
__device__ __forceinline__ void mma16816(float* c, const uint32_t* a, const uint32_t* b){
    asm volatile("mma.sync.aligned.m16n8k16.row.col.f32.f16.f16.f32 "
        "{%0,%1,%2,%3}, {%4,%5,%6,%7}, {%8,%9}, {%0,%1,%2,%3};"
        : "+f"(c[0]),"+f"(c[1]),"+f"(c[2]),"+f"(c[3])
        : "r"(a[0]),"r"(a[1]),"r"(a[2]),"r"(a[3]),"r"(b[0]),"r"(b[1]));
}
__device__ __forceinline__ void ldsm4(uint32_t* r, uint32_t addr){
    asm volatile("ldmatrix.sync.aligned.m8n8.x4.shared.b16 {%0,%1,%2,%3}, [%4];"
        : "=r"(r[0]),"=r"(r[1]),"=r"(r[2]),"=r"(r[3]) : "r"(addr));
}
__device__ __forceinline__ uint32_t cvta_smem(const void* p){
    uint32_t a; asm("{ .reg .u64 t; cvta.to.shared.u64 t, %1; cvt.u32.u64 %0, t; }":"=r"(a):"l"(p)); return a;
}
__device__ __forceinline__ void cpa16(uint32_t dst, const void* src){
    asm volatile("cp.async.cg.shared.global [%0], [%1], 16;"::"r"(dst),"l"(src));
}
#define CP_COMMIT asm volatile("cp.async.commit_group;")
#define CP_WAIT0  asm volatile("cp.async.wait_group 0;")
#define CP_WAIT1  asm volatile("cp.async.wait_group 1;")

__device__ __forceinline__ void stage_cp(uint32_t dst, const f16* src, int row0, int k0, int ld, int nrows){
    for (int i = threadIdx.x; i < nrows*8; i += 256){
        int r = i>>3, s = i&7;
        cpa16(dst + r*144 + s*16, src + (size_t)(row0+r)*ld + k0 + s*8);
    }
}
__device__ __forceinline__ int a_ldsm_off(int mrow0, int lane){
    return ((mrow0 + (lane&7) + ((lane>>3)&1)*8)*36 + (lane>>4)*4)*4;
}
__device__ __forceinline__ int b_ldsm_off(int nrow0, int lane){
    return ((nrow0 + (lane&7) + ((lane>>4)&1)*8)*36 + ((lane>>3)&1)*4)*4;
}

// ---- fp32 -> fp16 hi (x) ----
__global__ void __launch_bounds__(256)
conv_xh(const float* __restrict__ src, int n4)
{
    int i = blockIdx.x*256 + threadIdx.x;
    if (i >= n4) return;
    float4 v = ((const float4*)src)[i];
    f16 h[4];
    h[0]=__float2half_rn(v.x); h[1]=__float2half_rn(v.y);
    h[2]=__float2half_rn(v.z); h[3]=__float2half_rn(v.w);
    ((uint2*)g_xh)[i] = *(uint2*)h;
}
// ---- fp32 -> fp16 hi (all 5 weights, z-indexed) ----
__global__ void __launch_bounds__(256)
conv_w5(const float* __restrict__ w0, const float* __restrict__ w1,
        const float* __restrict__ w2, const float* __restrict__ w3,
        const float* __restrict__ w4, int n4)
{
    int i = blockIdx.x*256 + threadIdx.x;
    if (i >= n4) return;
    int z = blockIdx.y;
    const float* src = z==0?w0 : z==1?w1 : z==2?w2 : z==3?w3 : w4;
    float4 v = ((const float4*)src)[i];
    f16 h[4];
    h[0]=__float2half_rn(v.x); h[1]=__float2half_rn(v.y);
    h[2]=__float2half_rn(v.z); h[3]=__float2half_rn(v.w);
    ((uint2*)(g_w + (size_t)z*DD*DD))[i] = *(uint2*)h;
}

// ---- kNN mask (proven) ----
__global__ void __launch_bounds__(256)
build_mask(const float* __restrict__ dist)
{
    int b = blockIdx.x>>9, n = blockIdx.x&511, tid = threadIdx.x;
    unsigned char* mrow = g_mask + ((size_t)(b<<9)+n)*NN;
    if (n == 0){ for (int m=tid;m<NN;m+=256) mrow[m]=1; return; }
    __shared__ unsigned long long key[512];
    for (int m=tid;m<NN;m+=256){
        float v = (m==0)?0.0f:dist[(size_t)(b*511+(n-1))*511+(m-1)];
        key[m] = ((unsigned long long)__float_as_uint(v)<<32) | (unsigned)m;
    }
    __syncthreads();
    for (int k=2;k<=512;k<<=1) for (int j=k>>1;j>0;j>>=1){
        for (int i=tid;i<512;i+=256){
            int x = i^j;
            if (x>i){ bool up=((i&k)==0); unsigned long long a=key[i],c=key[x];
                if ((a>c)==up){ key[i]=c; key[x]=a; } }
        }
        __syncthreads();
    }
    for (int m=tid;m<NN;m+=256) mrow[m]=0;
    __syncthreads();
    for (int s=tid;s<KNN;s+=256) mrow[(int)(key[s]&511u)]=1;
    if (tid==0) mrow[0]=1;
}

// ---- big GEMM: 1-term fp16, cp.async dbuf, occupancy 2 ----
#define TILEW 4608
#define BUFW  (2*TILEW)
#define SMEM_BIG (2*BUFW*4)             // 73728 B
__global__ void __launch_bounds__(256, 2)
gemm_big(int asel, int widx0, const float* __restrict__ Bb0, const float* __restrict__ Bb1,
         const float* __restrict__ Bb2, const float* __restrict__ xres, int mode)
{
    extern __shared__ __align__(16) uint32_t sm[];
    const int bn=blockIdx.x, bm=blockIdx.y, z=blockIdx.z;
    const f16 *Ah = asel==0?g_xh: asel==1?g_mh:g_y1h;
    const f16 *Wh = g_w + (size_t)(widx0+z)*DD*DD;
    const float* Bb = z==0?Bb0 : z==1?Bb1 : Bb2;
    uint32_t sb = cvta_smem(sm);
    int tid=threadIdx.x, wid=tid>>5, lane=tid&31;
    int wm=wid&3, wn=wid>>2, tq=lane>>2, tr=lane&3;

    int aoff0 = a_ldsm_off(wm*32,      lane);
    int aoff1 = a_ldsm_off(wm*32+16,   lane);
    int boff0 = b_ldsm_off(wn*64,      lane);

    float acc[2][8][4];
    #pragma unroll
    for (int a=0;a<2;a++)
        #pragma unroll
        for (int b=0;b<8;b++)
            #pragma unroll
            for (int d=0;d<4;d++) acc[a][b][d]=0.0f;

    stage_cp(sb,           Ah, bm*128, 0, DD, 128);
    stage_cp(sb + TILEW*4, Wh, bn*128, 0, DD, 128);
    CP_COMMIT;

    for (int c = 0; c < 12; c++){
        int buf = c & 1;
        if (c < 11){
            uint32_t nb = sb + ((c+1)&1)*(BUFW*4);
            stage_cp(nb,           Ah, bm*128, (c+1)*64, DD, 128);
            stage_cp(nb + TILEW*4, Wh, bn*128, (c+1)*64, DD, 128);
            CP_COMMIT;
            CP_WAIT1;
        } else {
            CP_WAIT0;
        }
        __syncthreads();
        uint32_t bA = sb + buf*(BUFW*4);
        uint32_t bB = bA + TILEW*4;
        #pragma unroll
        for (int kk = 0; kk < 4; kk++){
            int kbyte = kk*32;
            uint32_t a_h[2][4], b_h[8][2];
            ldsm4(a_h[0], bA + aoff0 + kbyte);
            ldsm4(a_h[1], bA + aoff1 + kbyte);
            #pragma unroll
            for (int j=0;j<4;j++)
                ldsm4(&b_h[2*j][0], bB + boff0 + j*2304 + kbyte);
            #pragma unroll
            for (int am=0;am<2;am++)
                #pragma unroll
                for (int an=0;an<8;an++)
                    mma16816(acc[am][an], a_h[am], b_h[an]);
        }
        __syncthreads();
    }

    #pragma unroll
    for (int am=0;am<2;am++)
    #pragma unroll
    for (int rr=0;rr<2;rr++){
        int row = bm*128 + wm*32 + am*16 + tq + rr*8;
        #pragma unroll
        for (int an=0;an<8;an++){
            int col = bn*128 + wn*64 + an*8 + tr*2;
            float v0 = acc[am][an][rr*2]   + Bb[col];
            float v1 = acc[am][an][rr*2+1] + Bb[col+1];
            if (mode == 0){
                int b=row>>9, tok=row&511, h=col>>6, dk=col&63;
                if (z==0){
                    size_t off = ((size_t)(b*HH+h)*NN+tok)*DKK + dk;
                    f16 h0,l0,h1,l1; split2(v0,h0,l0); split2(v1,h1,l1);
                    *(uint32_t*)(g_qh+off) = pk(h0,h1);
                    *(uint32_t*)(g_ql+off) = pk(l0,l1);
                } else if (z==1){
                    size_t off = ((size_t)(b*HH+h)*NN+tok)*DKK + dk;
                    *(uint32_t*)(g_k+off) = pk2(v0,v1);
                } else {
                    size_t base = ((size_t)(b*HH+h)*DKK + dk)*NN + tok;
                    g_vt[base]      = __float2half_rn(v0);
                    g_vt[base + NN] = __float2half_rn(v1);
                }
            } else if (mode == 1){
                v0 = v0/(1.0f+__expf(-v0)); v1 = v1/(1.0f+__expf(-v1));
                size_t off = (size_t)row*DD + col;
                *(uint32_t*)(g_y1h+off) = pk2(v0,v1);
            } else {
                size_t off = (size_t)row*DD + col;
                float2 xr = *(const float2*)(xres+off);
                float2 o; o.x = v0+xr.x; o.y = v1+xr.y;
                *(float2*)(g_preln+off) = o;
            }
        }
    }
}

// ---- fused attention (proven R13, msg write hi-only) ----
#define QH0 0
#define QL0 2304
#define K0  4608
#define V0  23040
#define MSG0 39680
#define REDM 44032
#define REDS 44288
#define SMEM_ATT (44544*4)
__global__ void __launch_bounds__(256, 1)
attn_fused(float* __restrict__ attn)
{
    extern __shared__ __align__(16) uint32_t sm[];
    const int bm = blockIdx.x, z = blockIdx.y;
    const int bb = z/HH, hh = z%HH;
    uint32_t sb = cvta_smem(sm);
    int tid=threadIdx.x, wid=tid>>5, lane=tid&31;
    int wm=wid&1, wn=wid>>1, tq=lane>>2, tr=lane&3;

    stage_cp(sb + QH0*4, g_qh + (size_t)z*NN*DKK, bm*64, 0, DKK, 64);
    stage_cp(sb + QL0*4, g_ql + (size_t)z*NN*DKK, bm*64, 0, DKK, 64);
    stage_cp(sb + K0*4,  g_k  + (size_t)z*NN*DKK, 0,     0, DKK, 512);
    {
        const f16* Vt = g_vt + (size_t)z*DKK*NN;
        for (int i = tid; i < 4096; i += 256){
            int r = i>>6, s = i&63;
            cpa16(sb + V0*4 + r*1040 + s*16, Vt + (size_t)r*NN + s*8);
        }
    }
    CP_COMMIT; CP_WAIT0;
    __syncthreads();

    float acc[2][16][4];
    #pragma unroll
    for (int a=0;a<2;a++)
        #pragma unroll
        for (int b=0;b<16;b++)
            #pragma unroll
            for (int d=0;d<4;d++) acc[a][b][d]=0.0f;

    int aoff0 = a_ldsm_off(wm*32,    lane);
    int aoff1 = a_ldsm_off(wm*32+16, lane);
    int boff  = b_ldsm_off(wn*128,   lane);
    #pragma unroll
    for (int kk = 0; kk < 4; kk++){
        int kbyte = kk*32;
        uint32_t a_h[2][4], a_l[2][4], b_h[16][2];
        ldsm4(a_h[0], sb + QH0*4 + aoff0 + kbyte);
        ldsm4(a_h[1], sb + QH0*4 + aoff1 + kbyte);
        ldsm4(a_l[0], sb + QL0*4 + aoff0 + kbyte);
        ldsm4(a_l[1], sb + QL0*4 + aoff1 + kbyte);
        #pragma unroll
        for (int j=0;j<8;j++)
            ldsm4(&b_h[2*j][0], sb + K0*4 + boff + j*2304 + kbyte);
        #pragma unroll
        for (int am=0;am<2;am++)
            #pragma unroll
            for (int an=0;an<16;an++){
                mma16816(acc[am][an], a_h[am], b_h[an]);
                mma16816(acc[am][an], a_l[am], b_h[an]);
            }
    }

    #pragma unroll
    for (int am=0;am<2;am++)
    #pragma unroll
    for (int rr=0;rr<2;rr++){
        int row = bm*64 + wm*32 + am*16 + tq + rr*8;
        const unsigned char* mr = g_mask + ((size_t)(bb<<9)+row)*NN;
        #pragma unroll
        for (int an=0;an<16;an++){
            int col = wn*128 + an*8 + tr*2;
            acc[am][an][rr*2]   = mr[col]   ? acc[am][an][rr*2]*0.125f   : -1e12f;
            acc[am][an][rr*2+1] = mr[col+1] ? acc[am][an][rr*2+1]*0.125f : -1e12f;
        }
    }

    float* sRedM = (float*)(sm + REDM);
    float* sRedS = (float*)(sm + REDS);

    float mx[2][2];
    #pragma unroll
    for (int am=0;am<2;am++)
    #pragma unroll
    for (int rr=0;rr<2;rr++){
        float m = -1e30f;
        #pragma unroll
        for (int an=0;an<16;an++)
            m = fmaxf(m, fmaxf(acc[am][an][rr*2], acc[am][an][rr*2+1]));
        m = fmaxf(m, __shfl_xor_sync(0xffffffffu, m, 1));
        m = fmaxf(m, __shfl_xor_sync(0xffffffffu, m, 2));
        if (tr==0) sRedM[(wm*32+am*16+tq+rr*8)*4 + wn] = m;
        mx[am][rr] = m;
    }
    __syncthreads();
    #pragma unroll
    for (int am=0;am<2;am++)
    #pragma unroll
    for (int rr=0;rr<2;rr++){
        const float* p = sRedM + (wm*32+am*16+tq+rr*8)*4;
        mx[am][rr] = fmaxf(fmaxf(p[0],p[1]), fmaxf(p[2],p[3]));
    }

    float sumv[2][2];
    #pragma unroll
    for (int am=0;am<2;am++)
    #pragma unroll
    for (int rr=0;rr<2;rr++){
        float s = 0.0f;
        #pragma unroll
        for (int an=0;an<16;an++){
            float p0 = __expf(acc[am][an][rr*2]   - mx[am][rr]);
            float p1 = __expf(acc[am][an][rr*2+1] - mx[am][rr]);
            acc[am][an][rr*2] = p0; acc[am][an][rr*2+1] = p1;
            s += p0 + p1;
        }
        s += __shfl_xor_sync(0xffffffffu, s, 1);
        s += __shfl_xor_sync(0xffffffffu, s, 2);
        if (tr==0) sRedS[(wm*32+am*16+tq+rr*8)*4 + wn] = s;
        sumv[am][rr] = s;
    }
    __syncthreads();
    #pragma unroll
    for (int am=0;am<2;am++)
    #pragma unroll
    for (int rr=0;rr<2;rr++){
        const float* p = sRedS + (wm*32+am*16+tq+rr*8)*4;
        sumv[am][rr] = 1.0f/(p[0]+p[1]+p[2]+p[3]);
    }

    #pragma unroll
    for (int am=0;am<2;am++)
    #pragma unroll
    for (int rr=0;rr<2;rr++){
        int row = bm*64 + wm*32 + am*16 + tq + rr*8;
        float inv = sumv[am][rr];
        #pragma unroll
        for (int an=0;an<16;an++){
            float v0 = acc[am][an][rr*2]*inv, v1 = acc[am][an][rr*2+1]*inv;
            acc[am][an][rr*2] = v0; acc[am][an][rr*2+1] = v1;
            float2 o; o.x=v0; o.y=v1;
            *(float2*)(attn + ((size_t)z*NN+row)*NN + wn*128 + an*8 + tr*2) = o;
        }
    }

    float macc[2][8][4];
    #pragma unroll
    for (int a=0;a<2;a++)
        #pragma unroll
        for (int b=0;b<8;b++)
            #pragma unroll
            for (int d=0;d<4;d++) macc[a][b][d]=0.0f;

    int vlane = ((lane&7) + ((lane>>4)&1)*8)*1040 + ((lane>>3)&1)*16;
    int kwarp = wn*256;
    #pragma unroll
    for (int kj = 0; kj < 8; kj++){
        uint32_t aPh[2][4], aPl[2][4];
        #pragma unroll
        for (int am=0;am<2;am++){
            f16 h0,l0,h1,l1;
            split2(acc[am][2*kj][0],h0,l0);  split2(acc[am][2*kj][1],h1,l1);
            aPh[am][0]=pk(h0,h1); aPl[am][0]=pk(l0,l1);
            split2(acc[am][2*kj][2],h0,l0);  split2(acc[am][2*kj][3],h1,l1);
            aPh[am][1]=pk(h0,h1); aPl[am][1]=pk(l0,l1);
            split2(acc[am][2*kj+1][0],h0,l0); split2(acc[am][2*kj+1][1],h1,l1);
            aPh[am][2]=pk(h0,h1); aPl[am][2]=pk(l0,l1);
            split2(acc[am][2*kj+1][2],h0,l0); split2(acc[am][2*kj+1][3],h1,l1);
            aPh[am][3]=pk(h0,h1); aPl[am][3]=pk(l0,l1);
        }
        uint32_t bV[8][2];
        #pragma unroll
        for (int j=0;j<4;j++)
            ldsm4(&bV[2*j][0], sb + V0*4 + vlane + j*16*1040 + kwarp + kj*32);
        #pragma unroll
        for (int am=0;am<2;am++)
            #pragma unroll
            for (int an=0;an<8;an++){
                mma16816(macc[am][an], aPh[am], bV[an]);
                mma16816(macc[am][an], aPl[am], bV[an]);
            }
    }

    float* sMsg = (float*)(sm + MSG0);
    #pragma unroll
    for (int w=0; w<4; w++){
        if (wn == w){
            #pragma unroll
            for (int am=0;am<2;am++)
            #pragma unroll
            for (int rr=0;rr<2;rr++){
                int r = wm*32 + am*16 + tq + rr*8;
                #pragma unroll
                for (int an=0;an<8;an++){
                    float* p = sMsg + r*68 + an*8 + tr*2;
                    if (w==0){ p[0] = macc[am][an][rr*2]; p[1] = macc[am][an][rr*2+1]; }
                    else     { p[0]+= macc[am][an][rr*2]; p[1]+= macc[am][an][rr*2+1]; }
                }
            }
        }
        __syncthreads();
    }

    {
        int r = tid>>2, cq = (tid&3)*16;
        int tok = bm*64 + r;
        size_t base = ((size_t)(bb*NN+tok))*DD + hh*DKK + cq;
        #pragma unroll
        for (int i=0;i<8;i++){
            float v0 = sMsg[r*68 + cq + 2*i], v1 = sMsg[r*68 + cq + 2*i + 1];
            *(uint32_t*)(g_mh + base + 2*i) = pk2(v0,v1);
        }
    }
}

// ---- layernorm (proven) ----
__global__ void __launch_bounds__(256)
layernorm(const float* __restrict__ gam, const float* __restrict__ bet, float* __restrict__ out)
{
    int row = blockIdx.x, tid = threadIdx.x;
    const float* p = g_preln + (size_t)row*DD;
    float x0=p[tid], x1=p[tid+256], x2=p[tid+512];
    __shared__ float red[256];
    red[tid]=x0+x1+x2; __syncthreads();
    for (int o=128;o>0;o>>=1){ if (tid<o) red[tid]+=red[tid+o]; __syncthreads(); }
    float mu = red[0]*(1.0f/768.0f); __syncthreads();
    float d0=x0-mu, d1=x1-mu, d2=x2-mu;
    red[tid]=d0*d0+d1*d1+d2*d2; __syncthreads();
    for (int o=128;o>0;o>>=1){ if (tid<o) red[tid]+=red[tid+o]; __syncthreads(); }
    float inv = 1.0f/sqrtf(red[0]*(1.0f/768.0f)+1e-6f);
    float* o = out + (size_t)row*DD;
    o[tid]     = d0*inv*gam[tid]     + bet[tid];
    o[tid+256] = d1*inv*gam[tid+256] + bet[tid+256];
    o[tid+512] = d2*inv*gam[tid+512] + bet[tid+512];
}

extern "C" void kernel_launch(void* const* d_in, const int* in_sizes, int n_in,
                              void* d_out, int out_size)
{
    const float* x    = (const float*)d_in[0];
    const float* dist = (const float*)d_in[1];
    const float* q_w  = (const float*)d_in[2];
    const float* q_b  = (const float*)d_in[3];
    const float* k_w  = (const float*)d_in[4];
    const float* k_b  = (const float*)d_in[5];
    const float* v_w  = (const float*)d_in[6];
    const float* v_b  = (const float*)d_in[7];
    const float* s1_w = (const float*)d_in[8];
    const float* s1_b = (const float*)d_in[9];
    const float* s2_w = (const float*)d_in[10];
    const float* s2_b = (const float*)d_in[11];
    const float* ln_g = (const float*)d_in[12];
    const float* ln_b = (const float*)d_in[13];

    float* out  = (float*)d_out;
    float* attn = out + (size_t)MROWS*DD;

    cudaFuncSetAttribute(gemm_big,   cudaFuncAttributeMaxDynamicSharedMemorySize, SMEM_BIG);
    cudaFuncSetAttribute(attn_fused, cudaFuncAttributeMaxDynamicSharedMemorySize, SMEM_ATT);

    const size_t WSZ = (size_t)DD*DD;
    conv_xh<<<(MROWS*DD/4+255)/256, 256>>>(x, MROWS*DD/4);
    conv_w5<<<dim3((int)(WSZ/4+255)/256, 5), 256>>>(q_w, k_w, v_w, s1_w, s2_w, (int)(WSZ/4));

    build_mask<<<BB*NN, 256>>>(dist);

    gemm_big<<<dim3(DD/128, MROWS/128, 3), 256, SMEM_BIG>>>(0, 0, q_b, k_b, v_b, x, 0);
    attn_fused<<<dim3(NN/64, BHZ), 256, SMEM_ATT>>>(attn);
    gemm_big<<<dim3(DD/128, MROWS/128, 1), 256, SMEM_BIG>>>(1, 3, s1_b, s1_b, s1_b, x, 1);
    gemm_big<<<dim3(DD/128, MROWS/128, 1), 256, SMEM_BIG>>>(2, 4, s2_b, s2_b, s2_b, x, 2);
    layernorm<<<MROWS, 256>>>(ln_g, ln_b, out);
}